// round 13
// baseline (speedup 1.0000x reference)
#include <cuda_runtime.h>
#include <cuda_bf16.h>
#include <cstdint>

// Problem constants
#define D_MODEL 1024
#define N_HEADS 8
#define N_KV 2
#define HEAD_DIM 128
#define D_LAT 32
#define BATCH 2
#define SEQ 2048
#define M_TOK (BATCH*SEQ)          // 4096
#define KV_N 512                   // fused K|V width

// ---------------- scratch (4B words) ----------------
#define OFF_XH    0
#define OFF_XL    (OFF_XH   + 4096*512)
#define OFF_WQT_H (OFF_XL   + 4096*512)
#define OFF_WQT_L (OFF_WQT_H + 1024*512)
#define OFF_WOT_H (OFF_WQT_L + 1024*512)
#define OFF_WOT_L (OFF_WOT_H + 1024*512)
#define OFF_WKT_H (OFF_WOT_L + 1024*512)
#define OFF_WKT_L (OFF_WKT_H + 512*512)
#define OFF_QH    (OFF_WKT_L + 512*512)
#define OFF_QL    (OFF_QH   + 4096*512)
#define OFF_KVH   (OFF_QL   + 4096*512)
#define OFF_KVL   (OFF_KVH  + 4096*256)
#define OFF_VTH   (OFF_KVL  + 4096*256)
#define OFF_VTL   (OFF_VTH  + 2*2*128*1024)
#define OFF_YH    (OFF_VTL  + 2*2*128*1024)
#define OFF_YL    (OFF_YH   + 4096*512)
#define SCRATCH_WORDS (OFF_YL + 4096*512)
__device__ float g_scratch[SCRATCH_WORDS];

// ---------------- split-bf16 helpers ----------------
__device__ __forceinline__ void pksplit(float x, float y, uint32_t& hi, uint32_t& lo) {
    __nv_bfloat16 hx = __float2bfloat16(x), hy = __float2bfloat16(y);
    float rx = x - __bfloat162float(hx), ry = y - __bfloat162float(hy);
    hi = ((uint32_t)__bfloat16_as_ushort(hy) << 16) | (uint32_t)__bfloat16_as_ushort(hx);
    lo = ((uint32_t)__bfloat16_as_ushort(__float2bfloat16(ry)) << 16) |
         (uint32_t)__bfloat16_as_ushort(__float2bfloat16(rx));
}
#define HIP(u0,u1) __byte_perm((u0),(u1),0x5410)
#define LOP(u0,u1) __byte_perm((u0),(u1),0x7632)

__device__ __forceinline__ void mma16(float* c, uint32_t a0, uint32_t a1, uint32_t a2, uint32_t a3,
                                      uint32_t b0, uint32_t b1) {
    asm volatile(
        "mma.sync.aligned.m16n8k16.row.col.f32.bf16.bf16.f32 "
        "{%0,%1,%2,%3},{%4,%5,%6,%7},{%8,%9},{%0,%1,%2,%3};"
        : "+f"(c[0]), "+f"(c[1]), "+f"(c[2]), "+f"(c[3])
        : "r"(a0), "r"(a1), "r"(a2), "r"(a3), "r"(b0), "r"(b1));
}

__device__ __forceinline__ void cpa16(uint32_t dst_smem, const uint32_t* src) {
    asm volatile("{ .reg .u64 p; cvta.to.global.u64 p, %1; cp.async.ca.shared.global [%0], [p], 16; }"
                 :: "r"(dst_smem), "l"(src));
}

// ---------------- merged prep kernel ----------------
// grid 8512: [0,8192) pack_x | [8192,8320) packT(wq,scale) | [8320,8448) packT(wo,1) | [8448,8512) effw
__global__ __launch_bounds__(256) void prep_kernel(const float* __restrict__ x,
                                                   const float* __restrict__ wq,
                                                   const float* __restrict__ wo,
                                                   const float* __restrict__ wkd,
                                                   const float* __restrict__ wvd,
                                                   const float* __restrict__ wku,
                                                   const float* __restrict__ wvu,
                                                   uint32_t* __restrict__ xh,
                                                   uint32_t* __restrict__ xl,
                                                   uint32_t* __restrict__ wqth,
                                                   uint32_t* __restrict__ wqtl,
                                                   uint32_t* __restrict__ woth,
                                                   uint32_t* __restrict__ wotl,
                                                   uint32_t* __restrict__ wkth,
                                                   uint32_t* __restrict__ wktl,
                                                   float scale) {
    __shared__ union {
        struct { uint32_t sh[64][65]; uint32_t sl[64][65]; } pt;
        struct { float su[32][64]; float swd[128][33]; } ew;
    } S;
    const int bx = blockIdx.x;
    const int tid = threadIdx.x;

    if (bx < 8192) {
        // pack x into hi/lo planes (pairs along K)
        int idx = bx * 256 + tid;
        float2 v = *(const float2*)(x + 2 * (size_t)idx);
        uint32_t h, l;
        pksplit(v.x, v.y, h, l);
        xh[idx] = h; xl[idx] = l;
        return;
    }
    if (bx < 8448) {
        // transpose-pack weight [1024][1024] -> planes [N][512], scale folded
        const bool isq = bx < 8320;
        const int b = bx - (isq ? 8192 : 8320);
        const float* w = isq ? wq : wo;
        uint32_t* th = isq ? wqth : woth;
        uint32_t* tl = isq ? wqtl : wotl;
        const float sc = isq ? scale : 1.0f;
        const int kp0 = (b & 7) * 64;
        const int n0 = (b >> 3) * 64;
#pragma unroll
        for (int i = 0; i < 16; i++) {
            int idx = i * 256 + tid;
            int kp = idx >> 6, n = idx & 63;
            float a = w[(size_t)(2 * (kp0 + kp)) * 1024 + n0 + n] * sc;
            float bb = w[(size_t)(2 * (kp0 + kp) + 1) * 1024 + n0 + n] * sc;
            uint32_t h, l;
            pksplit(a, bb, h, l);
            S.pt.sh[kp][n] = h; S.pt.sl[kp][n] = l;
        }
        __syncthreads();
#pragma unroll
        for (int i = 0; i < 16; i++) {
            int idx = i * 256 + tid;
            int n = idx >> 6, kp = idx & 63;
            th[(size_t)(n0 + n) * 512 + kp0 + kp] = S.pt.sh[kp][n];
            tl[(size_t)(n0 + n) * 512 + kp0 + kp] = S.pt.sl[kp][n];
        }
        return;
    }
    // effective KV weights, transposed planes [512][512]
    {
        const int b = bx - 8448;
        const int c0b = (b & 7) * 64;
        const int n0  = (b >> 3) * 64;
        const int which = n0 >> 8;
        const int h = (n0 >> 7) & 1;
        const int d0 = n0 & 127;
        const float* wd = which ? wvd : wkd;
        const float* wu = which ? wvu : wku;
#pragma unroll
        for (int i = 0; i < 8; i++) {
            int idx = i * 256 + tid;
            int l = idx >> 6, dd = idx & 63;
            S.ew.su[l][dd] = wu[l * HEAD_DIM + d0 + dd];
        }
#pragma unroll
        for (int i = 0; i < 16; i++) {
            int idx = i * 256 + tid;
            int r = idx >> 5, l = idx & 31;
            S.ew.swd[r][l] = wd[(size_t)(2 * c0b + r) * (N_KV * D_LAT) + h * D_LAT + l];
        }
        __syncthreads();
        const int c0l = tid & 63;
        const int nb = tid >> 6;
#pragma unroll
        for (int i = 0; i < 16; i++) {
            int nn = nb * 16 + i;
            float s0 = 0.f, s1 = 0.f;
#pragma unroll
            for (int l = 0; l < 32; l++) {
                float u = S.ew.su[l][nn];
                s0 += S.ew.swd[2 * c0l][l] * u;
                s1 += S.ew.swd[2 * c0l + 1][l] * u;
            }
            uint32_t hi, lo;
            pksplit(s0, s1, hi, lo);
            wkth[(size_t)(n0 + nn) * 512 + c0b + c0l] = hi;
            wktl[(size_t)(n0 + nn) * 512 + c0b + c0l] = lo;
        }
    }
}

// ---------------- pre-packed plane GEMM core ----------------
#define PP_ST 20
#define PP_A (128*PP_ST)
#define PP_BUF (2*PP_A)
#define SM_PA 0
#define SM_PB (2*PP_BUF)
#define PP_SMEM (4*PP_BUF*4)    // 81920 bytes

#define PP_MAIN(Ah, Al, Bh, Bl, K, COL0)                                                    \
    extern __shared__ uint32_t sm[];                                                         \
    const uint32_t smb = (uint32_t)__cvta_generic_to_shared(sm);                             \
    const int tid = threadIdx.x;                                                             \
    const int w = tid >> 5;                                                                  \
    const int wm = w & 1;                                                                    \
    const int wn = w >> 1;                                                                   \
    const int lane = tid & 31;                                                               \
    const int g = lane >> 2;                                                                 \
    const int t = lane & 3;                                                                  \
    const int row0 = blockIdx.y * 128;                                                       \
    const int col0 = (COL0);                                                                 \
    const int kph = (K) >> 1;                                                                \
    auto fill = [&](int tt, int buf) {                                                       \
        const int kp0 = tt * 16;                                                             \
        _Pragma("unroll")                                                                    \
        for (int i = 0; i < 4; i++) {                                                        \
            int idx = i * 256 + tid;                                                         \
            int plane = idx >> 9;                                                            \
            int r = (idx >> 2) & 127;                                                        \
            int ch = (idx & 3) << 2;                                                         \
            const uint32_t* sa = (plane ? Al : Ah) + (size_t)(row0 + r) * kph + kp0 + ch;    \
            cpa16(smb + (SM_PA + buf * PP_BUF + plane * PP_A + r * PP_ST + ch) * 4, sa);     \
            const uint32_t* sb = (plane ? Bl : Bh) + (size_t)(col0 + r) * kph + kp0 + ch;    \
            cpa16(smb + (SM_PB + buf * PP_BUF + plane * PP_A + r * PP_ST + ch) * 4, sb);     \
        }                                                                                    \
    };                                                                                       \
    float c[4][4][4];                                                                        \
    _Pragma("unroll")                                                                        \
    for (int i = 0; i < 4; i++)                                                              \
        _Pragma("unroll")                                                                    \
        for (int j = 0; j < 4; j++)                                                          \
            _Pragma("unroll")                                                                \
            for (int r = 0; r < 4; r++) c[i][j][r] = 0.f;                                    \
    const int nt = (K) >> 5;                                                                 \
    fill(0, 0);                                                                              \
    asm volatile("cp.async.commit_group;");                                                  \
    asm volatile("cp.async.wait_group 0;");                                                  \
    __syncthreads();                                                                         \
    for (int tt = 0; tt < nt; tt++) {                                                        \
        if (tt + 1 < nt) {                                                                   \
            fill(tt + 1, (tt + 1) & 1);                                                      \
            asm volatile("cp.async.commit_group;");                                          \
        }                                                                                    \
        const uint32_t* AH = sm + SM_PA + (tt & 1) * PP_BUF;                                 \
        const uint32_t* AL = AH + PP_A;                                                      \
        const uint32_t* BH = sm + SM_PB + (tt & 1) * PP_BUF;                                 \
        const uint32_t* BL = BH + PP_A;                                                      \
        _Pragma("unroll")                                                                    \
        for (int kk = 0; kk < 2; kk++) {                                                     \
            const int kb = kk * 8 + t;                                                       \
            uint32_t ah[4][4], al[4][4], bh[4][2], bl[4][2];                                 \
            _Pragma("unroll")                                                                \
            for (int i = 0; i < 4; i++) {                                                    \
                int rb = wm * 64 + i * 16 + g;                                               \
                ah[i][0] = AH[rb * PP_ST + kb];                                              \
                ah[i][1] = AH[(rb + 8) * PP_ST + kb];                                        \
                ah[i][2] = AH[rb * PP_ST + kb + 4];                                          \
                ah[i][3] = AH[(rb + 8) * PP_ST + kb + 4];                                    \
                al[i][0] = AL[rb * PP_ST + kb];                                              \
                al[i][1] = AL[(rb + 8) * PP_ST + kb];                                        \
                al[i][2] = AL[rb * PP_ST + kb + 4];                                          \
                al[i][3] = AL[(rb + 8) * PP_ST + kb + 4];                                    \
            }                                                                                \
            _Pragma("unroll")                                                                \
            for (int j = 0; j < 4; j++) {                                                    \
                int cb = wn * 32 + j * 8 + g;                                                \
                bh[j][0] = BH[cb * PP_ST + kb];                                              \
                bh[j][1] = BH[cb * PP_ST + kb + 4];                                          \
                bl[j][0] = BL[cb * PP_ST + kb];                                              \
                bl[j][1] = BL[cb * PP_ST + kb + 4];                                          \
            }                                                                                \
            _Pragma("unroll")                                                                \
            for (int i = 0; i < 4; i++)                                                      \
                _Pragma("unroll")                                                            \
                for (int j = 0; j < 4; j++) {                                                \
                    mma16(c[i][j], ah[i][0], ah[i][1], ah[i][2], ah[i][3], bh[j][0], bh[j][1]); \
                    mma16(c[i][j], ah[i][0], ah[i][1], ah[i][2], ah[i][3], bl[j][0], bl[j][1]); \
                    mma16(c[i][j], al[i][0], al[i][1], al[i][2], al[i][3], bh[j][0], bh[j][1]); \
                }                                                                            \
        }                                                                                    \
        if (tt + 1 < nt) {                                                                   \
            asm volatile("cp.async.wait_group 0;");                                          \
            __syncthreads();                                                                 \
        }                                                                                    \
    }

// merged Q + KV projection (plane output). grid (12, 32): bx<8 -> Q, else KV.
__global__ __launch_bounds__(256) void mm_proj(const uint32_t* __restrict__ Ah,
                                               const uint32_t* __restrict__ Al,
                                               const uint32_t* __restrict__ wqh,
                                               const uint32_t* __restrict__ wql,
                                               const uint32_t* __restrict__ wkh,
                                               const uint32_t* __restrict__ wkl,
                                               uint32_t* __restrict__ qh,
                                               uint32_t* __restrict__ ql,
                                               uint32_t* __restrict__ kvh,
                                               uint32_t* __restrict__ kvl) {
    const bool isq = blockIdx.x < 8;
    const uint32_t* Bh = isq ? wqh : wkh;
    const uint32_t* Bl = isq ? wql : wkl;
    uint32_t* Ph = isq ? qh : kvh;
    uint32_t* Pl = isq ? ql : kvl;
    const int np = isq ? 512 : 256;
    PP_MAIN(Ah, Al, Bh, Bl, 1024, (isq ? blockIdx.x : blockIdx.x - 8) * 128)
#pragma unroll
    for (int i = 0; i < 4; i++) {
        int r = row0 + wm * 64 + i * 16 + g;
#pragma unroll
        for (int j = 0; j < 4; j++) {
            int cp = (col0 + wn * 32 + j * 8 + t * 2) >> 1;
            uint32_t h0, l0, h1, l1;
            pksplit(c[i][j][0], c[i][j][1], h0, l0);
            pksplit(c[i][j][2], c[i][j][3], h1, l1);
            Ph[(size_t)r * np + cp] = h0;
            Pl[(size_t)r * np + cp] = l0;
            Ph[(size_t)(r + 8) * np + cp] = h1;
            Pl[(size_t)(r + 8) * np + cp] = l1;
        }
    }
}

// fp32-output variant (out projection)
__global__ __launch_bounds__(256) void mm_pp_f32(int N, int K,
                                                 const uint32_t* __restrict__ Ah,
                                                 const uint32_t* __restrict__ Al,
                                                 const uint32_t* __restrict__ Bh,
                                                 const uint32_t* __restrict__ Bl,
                                                 float* __restrict__ C) {
    PP_MAIN(Ah, Al, Bh, Bl, K, blockIdx.x * 128)
#pragma unroll
    for (int i = 0; i < 4; i++) {
        int r = row0 + wm * 64 + i * 16 + g;
#pragma unroll
        for (int j = 0; j < 4; j++) {
            int cc = col0 + wn * 32 + j * 8 + t * 2;
            *(float2*)(C + (size_t)r * N + cc) = make_float2(c[i][j][0], c[i][j][1]);
            *(float2*)(C + (size_t)(r + 8) * N + cc) = make_float2(c[i][j][2], c[i][j][3]);
        }
    }
}

// ---------------- V transpose: KV planes [token][dpair] -> VT planes [d][tokenpair] ----------------
__global__ __launch_bounds__(256) void vtrans_kernel(const uint32_t* __restrict__ kvh,
                                                     const uint32_t* __restrict__ kvl,
                                                     uint32_t* __restrict__ vth,
                                                     uint32_t* __restrict__ vtl) {
    __shared__ uint32_t tile[64][65];
    const int t0 = blockIdx.x * 64;
    const int kvhd = blockIdx.y;
    const int b = blockIdx.z;
    const int tid = threadIdx.x;
#pragma unroll
    for (int p = 0; p < 2; p++) {
        const uint32_t* src = p ? kvl : kvh;
        uint32_t* dst = p ? vtl : vth;
#pragma unroll
        for (int i = 0; i < 16; i++) {
            int idx = i * 256 + tid;
            int r = idx >> 6, cx = idx & 63;
            tile[r][cx] = src[(size_t)(b * SEQ + t0 + r) * 256 + 128 + kvhd * 64 + cx];
        }
        __syncthreads();
#pragma unroll
        for (int i = 0; i < 16; i++) {
            int idx = i * 256 + tid;
            int d = idx >> 5, tpl = idx & 31;
            uint32_t u0 = tile[2 * tpl][d >> 1];
            uint32_t u1 = tile[2 * tpl + 1][d >> 1];
            uint32_t res = (d & 1) ? LOP(u0, u1) : HIP(u0, u1);
            dst[(size_t)((b * N_KV + kvhd) * 128 + d) * 1024 + (t0 >> 1) + tpl] = res;
        }
        __syncthreads();
    }
}

// ---------------- flash attention v4: BC=128, single-buffered K/V, pipelined fills ----------------
#define FQ_ST 68
#define FK_ST 68
#define FV_ST 68
#define SM4_QH 0
#define SM4_QL (128*FQ_ST)
#define SM4_K  (2*128*FQ_ST)
#define SM4_V  (SM4_K + 2*128*FK_ST)
#define FA4_SMEM ((SM4_V + 2*128*FV_ST)*4)     // 208896 bytes

__global__ __launch_bounds__(256, 1) void flash4_kernel(const uint32_t* __restrict__ qh,
                                                        const uint32_t* __restrict__ ql,
                                                        const uint32_t* __restrict__ kvh,
                                                        const uint32_t* __restrict__ kvl,
                                                        const uint32_t* __restrict__ vth,
                                                        const uint32_t* __restrict__ vtl,
                                                        uint32_t* __restrict__ yh,
                                                        uint32_t* __restrict__ yl) {
    extern __shared__ uint32_t sm[];
    const uint32_t smb = (uint32_t)__cvta_generic_to_shared(sm);

    const int qb = (SEQ / 128 - 1) - blockIdx.x;   // heavy tiles first
    const int hq = blockIdx.y;
    const int b  = blockIdx.z;
    const int kvhd = hq >> 2;
    const int tid = threadIdx.x;
    const int w = tid >> 5;
    const int lane = tid & 31;
    const int g = lane >> 2;
    const int t = lane & 3;
    const int q0 = qb * 128;

    // ---- prologue fills ----
#pragma unroll
    for (int i = 0; i < 16; i++) {
        int idx = i * 256 + tid;
        int plane = idx >> 11;
        int r = (idx >> 4) & 127;
        int ch = (idx & 15) << 2;
        const uint32_t* src = (plane ? ql : qh) + (size_t)(b * SEQ + q0 + r) * 512 + hq * 64 + ch;
        cpa16(smb + (SM4_QH + plane * (128 * FQ_ST) + r * FQ_ST + ch) * 4, src);
    }
    auto fillK = [&](int kt) {
#pragma unroll
        for (int i = 0; i < 16; i++) {
            int idx = i * 256 + tid;
            int plane = idx >> 11;
            int r = (idx >> 4) & 127;
            int ch = (idx & 15) << 2;
            const uint32_t* src = (plane ? kvl : kvh) +
                                  (size_t)(b * SEQ + kt * 128 + r) * 256 + kvhd * 64 + ch;
            cpa16(smb + (SM4_K + plane * (128 * FK_ST) + r * FK_ST + ch) * 4, src);
        }
    };
    auto fillV = [&](int kt) {
#pragma unroll
        for (int i = 0; i < 16; i++) {
            int idx = i * 256 + tid;
            int plane = idx >> 11;
            int d = (idx >> 4) & 127;
            int ch = (idx & 15) << 2;
            const uint32_t* src = (plane ? vtl : vth) +
                                  (size_t)((b * N_KV + kvhd) * 128 + d) * 1024 + kt * 64 + ch;
            cpa16(smb + (SM4_V + plane * (128 * FV_ST) + d * FV_ST + ch) * 4, src);
        }
    };
    fillK(0);
    fillV(0);
    asm volatile("cp.async.commit_group;");
    asm volatile("cp.async.wait_group 0;");
    __syncthreads();

    const uint32_t* QH = sm;
    const uint32_t* QL = sm + SM4_QL;
    const uint32_t* KH = sm + SM4_K;
    const uint32_t* KL = KH + 128 * FK_ST;
    const uint32_t* VH = sm + SM4_V;
    const uint32_t* VL = VH + 128 * FV_ST;

    float m0 = -1e30f, m1 = -1e30f, l0 = 0.f, l1 = 0.f;
    float o[16][4];
#pragma unroll
    for (int n = 0; n < 16; n++)
#pragma unroll
        for (int r = 0; r < 4; r++) o[n][r] = 0.f;

    const int rowg = q0 + w * 16 + g;
    const int rb = w * 16 + g;

    for (int kc = 0; kc <= qb; kc++) {
        // ---- S = Q @ K^T : warp tile 16 x 128 ----
        float s[16][4];
#pragma unroll
        for (int n = 0; n < 16; n++)
#pragma unroll
            for (int r = 0; r < 4; r++) s[n][r] = 0.f;

#pragma unroll
        for (int kt = 0; kt < 8; kt++) {
            const int kbase = kt * 8 + t;
            uint32_t ah0 = QH[rb * FQ_ST + kbase];
            uint32_t ah1 = QH[(rb + 8) * FQ_ST + kbase];
            uint32_t ah2 = QH[rb * FQ_ST + kbase + 4];
            uint32_t ah3 = QH[(rb + 8) * FQ_ST + kbase + 4];
            uint32_t al0 = QL[rb * FQ_ST + kbase];
            uint32_t al1 = QL[(rb + 8) * FQ_ST + kbase];
            uint32_t al2 = QL[rb * FQ_ST + kbase + 4];
            uint32_t al3 = QL[(rb + 8) * FQ_ST + kbase + 4];
#pragma unroll
            for (int n = 0; n < 16; n++) {
                const int cb = n * 8 + g;
                uint32_t bh0 = KH[cb * FK_ST + kbase];
                uint32_t bh1 = KH[cb * FK_ST + kbase + 4];
                uint32_t bl0 = KL[cb * FK_ST + kbase];
                uint32_t bl1 = KL[cb * FK_ST + kbase + 4];
                mma16(s[n], ah0, ah1, ah2, ah3, bh0, bh1);
                mma16(s[n], ah0, ah1, ah2, ah3, bl0, bl1);
                mma16(s[n], al0, al1, al2, al3, bh0, bh1);
            }
        }

        __syncthreads();                       // K consumed by all warps
        if (kc < qb) {
            fillK(kc + 1);
            asm volatile("cp.async.commit_group;");
        }

        // causal mask on the diagonal tile
        if (kc == qb) {
#pragma unroll
            for (int n = 0; n < 16; n++) {
                int c0 = kc * 128 + n * 8 + 2 * t;
                if (c0 > rowg)          s[n][0] = -1e30f;
                if (c0 + 1 > rowg)      s[n][1] = -1e30f;
                if (c0 > rowg + 8)      s[n][2] = -1e30f;
                if (c0 + 1 > rowg + 8)  s[n][3] = -1e30f;
            }
        }

        // ---- in-warp online softmax ----
        float mx0 = -1e30f, mx1 = -1e30f;
#pragma unroll
        for (int n = 0; n < 16; n++) {
            mx0 = fmaxf(mx0, fmaxf(s[n][0], s[n][1]));
            mx1 = fmaxf(mx1, fmaxf(s[n][2], s[n][3]));
        }
        mx0 = fmaxf(mx0, __shfl_xor_sync(0xffffffffu, mx0, 1));
        mx0 = fmaxf(mx0, __shfl_xor_sync(0xffffffffu, mx0, 2));
        mx1 = fmaxf(mx1, __shfl_xor_sync(0xffffffffu, mx1, 1));
        mx1 = fmaxf(mx1, __shfl_xor_sync(0xffffffffu, mx1, 2));
        float mn0 = fmaxf(m0, mx0), mn1 = fmaxf(m1, mx1);
        float a0 = __expf(m0 - mn0), a1 = __expf(m1 - mn1);
        m0 = mn0; m1 = mn1;
        float rs0 = 0.f, rs1 = 0.f;
#pragma unroll
        for (int n = 0; n < 16; n++) {
            s[n][0] = __expf(s[n][0] - mn0);
            s[n][1] = __expf(s[n][1] - mn0);
            s[n][2] = __expf(s[n][2] - mn1);
            s[n][3] = __expf(s[n][3] - mn1);
            rs0 += s[n][0] + s[n][1];
            rs1 += s[n][2] + s[n][3];
        }
        rs0 += __shfl_xor_sync(0xffffffffu, rs0, 1);
        rs0 += __shfl_xor_sync(0xffffffffu, rs0, 2);
        rs1 += __shfl_xor_sync(0xffffffffu, rs1, 1);
        rs1 += __shfl_xor_sync(0xffffffffu, rs1, 2);
        l0 = l0 * a0 + rs0;
        l1 = l1 * a1 + rs1;
#pragma unroll
        for (int n = 0; n < 16; n++) {
            o[n][0] *= a0; o[n][1] *= a0;
            o[n][2] *= a1; o[n][3] *= a1;
        }

        asm volatile("cp.async.wait_group 1;");  // own V(kc) arrival (K(kc+1) may fly)
        __syncthreads();                          // everyone's V(kc) visible

        // ---- O += P @ V, two kt-halves to bound register pressure ----
#pragma unroll
        for (int half = 0; half < 2; half++) {
            uint32_t phi[4][4], plo[4][4];
#pragma unroll
            for (int q = 0; q < 4; q++) {
                int kt = half * 4 + q;
                pksplit(s[2 * kt][0], s[2 * kt][1], phi[q][0], plo[q][0]);
                pksplit(s[2 * kt][2], s[2 * kt][3], phi[q][1], plo[q][1]);
                pksplit(s[2 * kt + 1][0], s[2 * kt + 1][1], phi[q][2], plo[q][2]);
                pksplit(s[2 * kt + 1][2], s[2 * kt + 1][3], phi[q][3], plo[q][3]);
            }
#pragma unroll
            for (int q = 0; q < 4; q++) {
                const int kb = (half * 4 + q) * 8 + t;
#pragma unroll
                for (int n = 0; n < 16; n++) {
                    const int nb = n * 8 + g;
                    uint32_t bh0 = VH[nb * FV_ST + kb];
                    uint32_t bh1 = VH[nb * FV_ST + kb + 4];
                    uint32_t bl0 = VL[nb * FV_ST + kb];
                    uint32_t bl1 = VL[nb * FV_ST + kb + 4];
                    mma16(o[n], phi[q][0], phi[q][1], phi[q][2], phi[q][3], bh0, bh1);
                    mma16(o[n], phi[q][0], phi[q][1], phi[q][2], phi[q][3], bl0, bl1);
                    mma16(o[n], plo[q][0], plo[q][1], plo[q][2], plo[q][3], bh0, bh1);
                }
            }
        }

        __syncthreads();                       // V consumed by all warps
        if (kc < qb) {
            fillV(kc + 1);
            asm volatile("cp.async.commit_group;");
        }
        asm volatile("cp.async.wait_group 1;");  // own K(kc+1) arrival (V(kc+1) may fly)
        __syncthreads();                          // everyone's K(kc+1) visible
    }

    // epilogue: emit y planes (pairs along d == out-proj K)
    const int row = w * 16 + g;
    float inv0 = 1.f / l0, inv1 = 1.f / l1;
    uint32_t* yh0 = yh + (size_t)(b * SEQ + q0 + row) * 512;
    uint32_t* yl0 = yl + (size_t)(b * SEQ + q0 + row) * 512;
    uint32_t* yh1 = yh + (size_t)(b * SEQ + q0 + row + 8) * 512;
    uint32_t* yl1 = yl + (size_t)(b * SEQ + q0 + row + 8) * 512;
#pragma unroll
    for (int n = 0; n < 16; n++) {
        int cp = hq * 64 + n * 4 + t;
        uint32_t h, l;
        pksplit(o[n][0] * inv0, o[n][1] * inv0, h, l);
        yh0[cp] = h; yl0[cp] = l;
        pksplit(o[n][2] * inv1, o[n][3] * inv1, h, l);
        yh1[cp] = h; yl1[cp] = l;
    }
}

// ---------------- launch ----------------
extern "C" void kernel_launch(void* const* d_in, const int* in_sizes, int n_in,
                              void* d_out, int out_size) {
    const float* x   = (const float*)d_in[0];
    const float* wq  = (const float*)d_in[1];
    const float* wkd = (const float*)d_in[2];
    const float* wvd = (const float*)d_in[3];
    const float* wku = (const float*)d_in[4];
    const float* wvu = (const float*)d_in[5];
    const float* wo  = (const float*)d_in[6];
    float* out = (float*)d_out;

    float* scratch = nullptr;
    cudaGetSymbolAddress((void**)&scratch, g_scratch);
    uint32_t* xh   = (uint32_t*)(scratch + OFF_XH);
    uint32_t* xl   = (uint32_t*)(scratch + OFF_XL);
    uint32_t* wqth = (uint32_t*)(scratch + OFF_WQT_H);
    uint32_t* wqtl = (uint32_t*)(scratch + OFF_WQT_L);
    uint32_t* woth = (uint32_t*)(scratch + OFF_WOT_H);
    uint32_t* wotl = (uint32_t*)(scratch + OFF_WOT_L);
    uint32_t* wkth = (uint32_t*)(scratch + OFF_WKT_H);
    uint32_t* wktl = (uint32_t*)(scratch + OFF_WKT_L);
    uint32_t* qhg  = (uint32_t*)(scratch + OFF_QH);
    uint32_t* qlg  = (uint32_t*)(scratch + OFF_QL);
    uint32_t* kvhg = (uint32_t*)(scratch + OFF_KVH);
    uint32_t* kvlg = (uint32_t*)(scratch + OFF_KVL);
    uint32_t* vthg = (uint32_t*)(scratch + OFF_VTH);
    uint32_t* vtlg = (uint32_t*)(scratch + OFF_VTL);
    uint32_t* yhg  = (uint32_t*)(scratch + OFF_YH);
    uint32_t* ylg  = (uint32_t*)(scratch + OFF_YL);

    const float scale = 0.08838834764831845f;   // 1/sqrt(128)

    // merged prep: pack x, transpose-pack wq/wo, effective KV weights
    prep_kernel<<<8512, 256>>>(x, wq, wo, wkd, wvd, wku, wvu,
                               xh, xl, wqth, wqtl, woth, wotl, wkth, wktl, scale);

    cudaFuncSetAttribute(mm_proj, cudaFuncAttributeMaxDynamicSharedMemorySize, PP_SMEM);
    cudaFuncSetAttribute(mm_pp_f32, cudaFuncAttributeMaxDynamicSharedMemorySize, PP_SMEM);

    // merged Q + KV projections
    mm_proj<<<dim3(12, 32), 256, PP_SMEM>>>(xh, xl, wqth, wqtl, wkth, wktl,
                                            qhg, qlg, kvhg, kvlg);

    vtrans_kernel<<<dim3(SEQ / 64, N_KV, BATCH), 256>>>(kvhg, kvlg, vthg, vtlg);

    cudaFuncSetAttribute(flash4_kernel, cudaFuncAttributeMaxDynamicSharedMemorySize, FA4_SMEM);
    flash4_kernel<<<dim3(SEQ / 128, N_HEADS, BATCH), 256, FA4_SMEM>>>(qhg, qlg, kvhg, kvlg,
                                                                      vthg, vtlg, yhg, ylg);

    // output projection
    mm_pp_f32<<<dim3(8, 32), 256, PP_SMEM>>>(1024, 1024, yhg, ylg, woth, wotl, out);
}

// round 15
// speedup vs baseline: 1.0562x; 1.0562x over previous
#include <cuda_runtime.h>
#include <cuda_bf16.h>
#include <cstdint>

// Problem constants
#define D_MODEL 1024
#define N_HEADS 8
#define N_KV 2
#define HEAD_DIM 128
#define D_LAT 32
#define BATCH 2
#define SEQ 2048
#define M_TOK (BATCH*SEQ)          // 4096
#define KV_N 512                   // fused K|V width

// ---------------- scratch (4B words) ----------------
#define OFF_XH    0
#define OFF_XL    (OFF_XH   + 4096*512)
#define OFF_WQT_H (OFF_XL   + 4096*512)
#define OFF_WQT_L (OFF_WQT_H + 1024*512)
#define OFF_WOT_H (OFF_WQT_L + 1024*512)
#define OFF_WOT_L (OFF_WOT_H + 1024*512)
#define OFF_WKT_H (OFF_WOT_L + 1024*512)
#define OFF_WKT_L (OFF_WKT_H + 512*512)
#define OFF_QH    (OFF_WKT_L + 512*512)
#define OFF_QL    (OFF_QH   + 4096*512)
#define OFF_KVH   (OFF_QL   + 4096*512)
#define OFF_KVL   (OFF_KVH  + 4096*256)
#define OFF_VTH   (OFF_KVL  + 4096*256)
#define OFF_VTL   (OFF_VTH  + 2*2*128*1024)
#define OFF_YH    (OFF_VTL  + 2*2*128*1024)
#define OFF_YL    (OFF_YH   + 4096*512)
#define SCRATCH_WORDS (OFF_YL + 4096*512)
__device__ float g_scratch[SCRATCH_WORDS];

// ---------------- split-bf16 helpers ----------------
__device__ __forceinline__ void pksplit(float x, float y, uint32_t& hi, uint32_t& lo) {
    __nv_bfloat16 hx = __float2bfloat16(x), hy = __float2bfloat16(y);
    float rx = x - __bfloat162float(hx), ry = y - __bfloat162float(hy);
    hi = ((uint32_t)__bfloat16_as_ushort(hy) << 16) | (uint32_t)__bfloat16_as_ushort(hx);
    lo = ((uint32_t)__bfloat16_as_ushort(__float2bfloat16(ry)) << 16) |
         (uint32_t)__bfloat16_as_ushort(__float2bfloat16(rx));
}
#define HIP(u0,u1) __byte_perm((u0),(u1),0x5410)
#define LOP(u0,u1) __byte_perm((u0),(u1),0x7632)

__device__ __forceinline__ void mma16(float* c, uint32_t a0, uint32_t a1, uint32_t a2, uint32_t a3,
                                      uint32_t b0, uint32_t b1) {
    asm volatile(
        "mma.sync.aligned.m16n8k16.row.col.f32.bf16.bf16.f32 "
        "{%0,%1,%2,%3},{%4,%5,%6,%7},{%8,%9},{%0,%1,%2,%3};"
        : "+f"(c[0]), "+f"(c[1]), "+f"(c[2]), "+f"(c[3])
        : "r"(a0), "r"(a1), "r"(a2), "r"(a3), "r"(b0), "r"(b1));
}

__device__ __forceinline__ void cpa16(uint32_t dst_smem, const uint32_t* src) {
    asm volatile("{ .reg .u64 p; cvta.to.global.u64 p, %1; cp.async.ca.shared.global [%0], [p], 16; }"
                 :: "r"(dst_smem), "l"(src));
}

// ---------------- prep: pack x into hi/lo planes (pairs along K) ----------------
__global__ void pack_x_kernel(const float* __restrict__ x,
                              uint32_t* __restrict__ xh, uint32_t* __restrict__ xl) {
    int idx = blockIdx.x * blockDim.x + threadIdx.x;    // 4096*512
    float2 v = *(const float2*)(x + 2 * (size_t)idx);
    uint32_t h, l;
    pksplit(v.x, v.y, h, l);
    xh[idx] = h; xl[idx] = l;
}

// ---------------- prep: transpose-pack weight [1024][N] -> planes [N][512], scale folded ----------------
__global__ __launch_bounds__(256) void packT_kernel(const float* __restrict__ w, int N,
                                                    uint32_t* __restrict__ th,
                                                    uint32_t* __restrict__ tl,
                                                    float scale) {
    __shared__ uint32_t sh[64][65];
    __shared__ uint32_t sl[64][65];
    const int kp0 = blockIdx.x * 64;   // kpair base (kpair < 512)
    const int n0 = blockIdx.y * 64;
    const int tid = threadIdx.x;
#pragma unroll
    for (int i = 0; i < 16; i++) {
        int idx = i * 256 + tid;
        int kp = idx >> 6, n = idx & 63;
        float a = w[(size_t)(2 * (kp0 + kp)) * N + n0 + n] * scale;
        float b = w[(size_t)(2 * (kp0 + kp) + 1) * N + n0 + n] * scale;
        uint32_t h, l;
        pksplit(a, b, h, l);
        sh[kp][n] = h; sl[kp][n] = l;
    }
    __syncthreads();
#pragma unroll
    for (int i = 0; i < 16; i++) {
        int idx = i * 256 + tid;
        int n = idx >> 6, kp = idx & 63;
        th[(size_t)(n0 + n) * 512 + kp0 + kp] = sh[kp][n];
        tl[(size_t)(n0 + n) * 512 + kp0 + kp] = sl[kp][n];
    }
}

// ---------------- prep: effective KV weights, transposed planes [512][512] ----------------
__global__ __launch_bounds__(256) void eff_weightsT_kernel(const float* __restrict__ wkd,
                                                           const float* __restrict__ wvd,
                                                           const float* __restrict__ wku,
                                                           const float* __restrict__ wvu,
                                                           uint32_t* __restrict__ th,
                                                           uint32_t* __restrict__ tl) {
    __shared__ float su[32][64];       // wu[l][d0+dd]
    __shared__ float swd[128][33];     // wd[cbase+r][h*32+l]
    const int c0b = blockIdx.x * 64;   // c0 pair base
    const int n0  = blockIdx.y * 64;   // output row base
    const int which = n0 >> 8;
    const int h = (n0 >> 7) & 1;
    const int d0 = n0 & 127;
    const float* wd = which ? wvd : wkd;
    const float* wu = which ? wvu : wku;
    const int tid = threadIdx.x;

#pragma unroll
    for (int i = 0; i < 8; i++) {
        int idx = i * 256 + tid;
        int l = idx >> 6, dd = idx & 63;
        su[l][dd] = wu[l * HEAD_DIM + d0 + dd];
    }
#pragma unroll
    for (int i = 0; i < 16; i++) {
        int idx = i * 256 + tid;
        int r = idx >> 5, l = idx & 31;
        swd[r][l] = wd[(size_t)(2 * c0b + r) * (N_KV * D_LAT) + h * D_LAT + l];
    }
    __syncthreads();

    const int c0l = tid & 63;
    const int nb = tid >> 6;
#pragma unroll
    for (int i = 0; i < 16; i++) {
        int nn = nb * 16 + i;
        float s0 = 0.f, s1 = 0.f;
#pragma unroll
        for (int l = 0; l < 32; l++) {
            float u = su[l][nn];
            s0 += swd[2 * c0l][l] * u;
            s1 += swd[2 * c0l + 1][l] * u;
        }
        uint32_t hi, lo;
        pksplit(s0, s1, hi, lo);
        th[(size_t)(n0 + nn) * 512 + c0b + c0l] = hi;
        tl[(size_t)(n0 + nn) * 512 + c0b + c0l] = lo;
    }
}

// ---------------- pre-packed plane GEMM core ----------------
#define PP_ST 20
#define PP_A (128*PP_ST)
#define PP_BUF (2*PP_A)
#define SM_PA 0
#define SM_PB (2*PP_BUF)
#define PP_SMEM (4*PP_BUF*4)    // 81920 bytes

#define PP_MAIN(Ah, Al, Bh, Bl, K, COL0)                                                    \
    extern __shared__ uint32_t sm[];                                                         \
    const uint32_t smb = (uint32_t)__cvta_generic_to_shared(sm);                             \
    const int tid = threadIdx.x;                                                             \
    const int w = tid >> 5;                                                                  \
    const int wm = w & 1;                                                                    \
    const int wn = w >> 1;                                                                   \
    const int lane = tid & 31;                                                               \
    const int g = lane >> 2;                                                                 \
    const int t = lane & 3;                                                                  \
    const int row0 = blockIdx.y * 128;                                                       \
    const int col0 = (COL0);                                                                 \
    const int kph = (K) >> 1;                                                                \
    auto fill = [&](int tt, int buf) {                                                       \
        const int kp0 = tt * 16;                                                             \
        _Pragma("unroll")                                                                    \
        for (int i = 0; i < 4; i++) {                                                        \
            int idx = i * 256 + tid;                                                         \
            int plane = idx >> 9;                                                            \
            int r = (idx >> 2) & 127;                                                        \
            int ch = (idx & 3) << 2;                                                         \
            const uint32_t* sa = (plane ? Al : Ah) + (size_t)(row0 + r) * kph + kp0 + ch;    \
            cpa16(smb + (SM_PA + buf * PP_BUF + plane * PP_A + r * PP_ST + ch) * 4, sa);     \
            const uint32_t* sb = (plane ? Bl : Bh) + (size_t)(col0 + r) * kph + kp0 + ch;    \
            cpa16(smb + (SM_PB + buf * PP_BUF + plane * PP_A + r * PP_ST + ch) * 4, sb);     \
        }                                                                                    \
    };                                                                                       \
    float c[4][4][4];                                                                        \
    _Pragma("unroll")                                                                        \
    for (int i = 0; i < 4; i++)                                                              \
        _Pragma("unroll")                                                                    \
        for (int j = 0; j < 4; j++)                                                          \
            _Pragma("unroll")                                                                \
            for (int r = 0; r < 4; r++) c[i][j][r] = 0.f;                                    \
    const int nt = (K) >> 5;                                                                 \
    fill(0, 0);                                                                              \
    asm volatile("cp.async.commit_group;");                                                  \
    asm volatile("cp.async.wait_group 0;");                                                  \
    __syncthreads();                                                                         \
    for (int tt = 0; tt < nt; tt++) {                                                        \
        if (tt + 1 < nt) {                                                                   \
            fill(tt + 1, (tt + 1) & 1);                                                      \
            asm volatile("cp.async.commit_group;");                                          \
        }                                                                                    \
        const uint32_t* AH = sm + SM_PA + (tt & 1) * PP_BUF;                                 \
        const uint32_t* AL = AH + PP_A;                                                      \
        const uint32_t* BH = sm + SM_PB + (tt & 1) * PP_BUF;                                 \
        const uint32_t* BL = BH + PP_A;                                                      \
        _Pragma("unroll")                                                                    \
        for (int kk = 0; kk < 2; kk++) {                                                     \
            const int kb = kk * 8 + t;                                                       \
            uint32_t ah[4][4], al[4][4], bh[4][2], bl[4][2];                                 \
            _Pragma("unroll")                                                                \
            for (int i = 0; i < 4; i++) {                                                    \
                int rb = wm * 64 + i * 16 + g;                                               \
                ah[i][0] = AH[rb * PP_ST + kb];                                              \
                ah[i][1] = AH[(rb + 8) * PP_ST + kb];                                        \
                ah[i][2] = AH[rb * PP_ST + kb + 4];                                          \
                ah[i][3] = AH[(rb + 8) * PP_ST + kb + 4];                                    \
                al[i][0] = AL[rb * PP_ST + kb];                                              \
                al[i][1] = AL[(rb + 8) * PP_ST + kb];                                        \
                al[i][2] = AL[rb * PP_ST + kb + 4];                                          \
                al[i][3] = AL[(rb + 8) * PP_ST + kb + 4];                                    \
            }                                                                                \
            _Pragma("unroll")                                                                \
            for (int j = 0; j < 4; j++) {                                                    \
                int cb = wn * 32 + j * 8 + g;                                                \
                bh[j][0] = BH[cb * PP_ST + kb];                                              \
                bh[j][1] = BH[cb * PP_ST + kb + 4];                                          \
                bl[j][0] = BL[cb * PP_ST + kb];                                              \
                bl[j][1] = BL[cb * PP_ST + kb + 4];                                          \
            }                                                                                \
            _Pragma("unroll")                                                                \
            for (int i = 0; i < 4; i++)                                                      \
                _Pragma("unroll")                                                            \
                for (int j = 0; j < 4; j++) {                                                \
                    mma16(c[i][j], ah[i][0], ah[i][1], ah[i][2], ah[i][3], bh[j][0], bh[j][1]); \
                    mma16(c[i][j], ah[i][0], ah[i][1], ah[i][2], ah[i][3], bl[j][0], bl[j][1]); \
                    mma16(c[i][j], al[i][0], al[i][1], al[i][2], al[i][3], bh[j][0], bh[j][1]); \
                }                                                                            \
        }                                                                                    \
        if (tt + 1 < nt) {                                                                   \
            asm volatile("cp.async.wait_group 0;");                                          \
            __syncthreads();                                                                 \
        }                                                                                    \
    }

// merged Q + KV projection (plane output). grid (12, 32): bx<8 -> Q, else KV.
__global__ __launch_bounds__(256) void mm_proj(const uint32_t* __restrict__ Ah,
                                               const uint32_t* __restrict__ Al,
                                               const uint32_t* __restrict__ wqh,
                                               const uint32_t* __restrict__ wql,
                                               const uint32_t* __restrict__ wkh,
                                               const uint32_t* __restrict__ wkl,
                                               uint32_t* __restrict__ qh,
                                               uint32_t* __restrict__ ql,
                                               uint32_t* __restrict__ kvh,
                                               uint32_t* __restrict__ kvl) {
    const bool isq = blockIdx.x < 8;
    const uint32_t* Bh = isq ? wqh : wkh;
    const uint32_t* Bl = isq ? wql : wkl;
    uint32_t* Ph = isq ? qh : kvh;
    uint32_t* Pl = isq ? ql : kvl;
    const int np = isq ? 512 : 256;
    PP_MAIN(Ah, Al, Bh, Bl, 1024, (isq ? blockIdx.x : blockIdx.x - 8) * 128)
#pragma unroll
    for (int i = 0; i < 4; i++) {
        int r = row0 + wm * 64 + i * 16 + g;
#pragma unroll
        for (int j = 0; j < 4; j++) {
            int cp = (col0 + wn * 32 + j * 8 + t * 2) >> 1;
            uint32_t h0, l0, h1, l1;
            pksplit(c[i][j][0], c[i][j][1], h0, l0);
            pksplit(c[i][j][2], c[i][j][3], h1, l1);
            Ph[(size_t)r * np + cp] = h0;
            Pl[(size_t)r * np + cp] = l0;
            Ph[(size_t)(r + 8) * np + cp] = h1;
            Pl[(size_t)(r + 8) * np + cp] = l1;
        }
    }
}

// fp32-output variant (out projection)
__global__ __launch_bounds__(256) void mm_pp_f32(int N, int K,
                                                 const uint32_t* __restrict__ Ah,
                                                 const uint32_t* __restrict__ Al,
                                                 const uint32_t* __restrict__ Bh,
                                                 const uint32_t* __restrict__ Bl,
                                                 float* __restrict__ C) {
    PP_MAIN(Ah, Al, Bh, Bl, K, blockIdx.x * 128)
#pragma unroll
    for (int i = 0; i < 4; i++) {
        int r = row0 + wm * 64 + i * 16 + g;
#pragma unroll
        for (int j = 0; j < 4; j++) {
            int cc = col0 + wn * 32 + j * 8 + t * 2;
            *(float2*)(C + (size_t)r * N + cc) = make_float2(c[i][j][0], c[i][j][1]);
            *(float2*)(C + (size_t)(r + 8) * N + cc) = make_float2(c[i][j][2], c[i][j][3]);
        }
    }
}

// ---------------- V transpose: KV planes [token][dpair] -> VT planes [d][tokenpair] ----------------
__global__ __launch_bounds__(256) void vtrans_kernel(const uint32_t* __restrict__ kvh,
                                                     const uint32_t* __restrict__ kvl,
                                                     uint32_t* __restrict__ vth,
                                                     uint32_t* __restrict__ vtl) {
    __shared__ uint32_t tile[64][65];
    const int t0 = blockIdx.x * 64;
    const int kvhd = blockIdx.y;
    const int b = blockIdx.z;
    const int tid = threadIdx.x;
#pragma unroll
    for (int p = 0; p < 2; p++) {
        const uint32_t* src = p ? kvl : kvh;
        uint32_t* dst = p ? vtl : vth;
#pragma unroll
        for (int i = 0; i < 16; i++) {
            int idx = i * 256 + tid;
            int r = idx >> 6, cx = idx & 63;
            tile[r][cx] = src[(size_t)(b * SEQ + t0 + r) * 256 + 128 + kvhd * 64 + cx];
        }
        __syncthreads();
#pragma unroll
        for (int i = 0; i < 16; i++) {
            int idx = i * 256 + tid;
            int d = idx >> 5, tpl = idx & 31;
            uint32_t u0 = tile[2 * tpl][d >> 1];
            uint32_t u1 = tile[2 * tpl + 1][d >> 1];
            uint32_t res = (d & 1) ? LOP(u0, u1) : HIP(u0, u1);
            dst[(size_t)((b * N_KV + kvhd) * 128 + d) * 1024 + (t0 >> 1) + tpl] = res;
        }
        __syncthreads();
    }
}

// ---------------- flash attention v4: BC=128, single-buffered K/V, pipelined fills ----------------
#define FQ_ST 68
#define FK_ST 68
#define FV_ST 68
#define SM4_QH 0
#define SM4_QL (128*FQ_ST)
#define SM4_K  (2*128*FQ_ST)
#define SM4_V  (SM4_K + 2*128*FK_ST)
#define FA4_SMEM ((SM4_V + 2*128*FV_ST)*4)     // 208896 bytes

__global__ __launch_bounds__(256, 1) void flash4_kernel(const uint32_t* __restrict__ qh,
                                                        const uint32_t* __restrict__ ql,
                                                        const uint32_t* __restrict__ kvh,
                                                        const uint32_t* __restrict__ kvl,
                                                        const uint32_t* __restrict__ vth,
                                                        const uint32_t* __restrict__ vtl,
                                                        uint32_t* __restrict__ yh,
                                                        uint32_t* __restrict__ yl) {
    extern __shared__ uint32_t sm[];
    const uint32_t smb = (uint32_t)__cvta_generic_to_shared(sm);

    const int qb = (SEQ / 128 - 1) - blockIdx.x;   // heavy tiles first
    const int hq = blockIdx.y;
    const int b  = blockIdx.z;
    const int kvhd = hq >> 2;
    const int tid = threadIdx.x;
    const int w = tid >> 5;
    const int lane = tid & 31;
    const int g = lane >> 2;
    const int t = lane & 3;
    const int q0 = qb * 128;

    // ---- prologue fills ----
#pragma unroll
    for (int i = 0; i < 16; i++) {
        int idx = i * 256 + tid;
        int plane = idx >> 11;
        int r = (idx >> 4) & 127;
        int ch = (idx & 15) << 2;
        const uint32_t* src = (plane ? ql : qh) + (size_t)(b * SEQ + q0 + r) * 512 + hq * 64 + ch;
        cpa16(smb + (SM4_QH + plane * (128 * FQ_ST) + r * FQ_ST + ch) * 4, src);
    }
    auto fillK = [&](int kt) {
#pragma unroll
        for (int i = 0; i < 16; i++) {
            int idx = i * 256 + tid;
            int plane = idx >> 11;
            int r = (idx >> 4) & 127;
            int ch = (idx & 15) << 2;
            const uint32_t* src = (plane ? kvl : kvh) +
                                  (size_t)(b * SEQ + kt * 128 + r) * 256 + kvhd * 64 + ch;
            cpa16(smb + (SM4_K + plane * (128 * FK_ST) + r * FK_ST + ch) * 4, src);
        }
    };
    auto fillV = [&](int kt) {
#pragma unroll
        for (int i = 0; i < 16; i++) {
            int idx = i * 256 + tid;
            int plane = idx >> 11;
            int d = (idx >> 4) & 127;
            int ch = (idx & 15) << 2;
            const uint32_t* src = (plane ? vtl : vth) +
                                  (size_t)((b * N_KV + kvhd) * 128 + d) * 1024 + kt * 64 + ch;
            cpa16(smb + (SM4_V + plane * (128 * FV_ST) + d * FV_ST + ch) * 4, src);
        }
    };
    fillK(0);
    fillV(0);
    asm volatile("cp.async.commit_group;");
    asm volatile("cp.async.wait_group 0;");
    __syncthreads();

    const uint32_t* QH = sm;
    const uint32_t* QL = sm + SM4_QL;
    const uint32_t* KH = sm + SM4_K;
    const uint32_t* KL = KH + 128 * FK_ST;
    const uint32_t* VH = sm + SM4_V;
    const uint32_t* VL = VH + 128 * FV_ST;

    float m0 = -1e30f, m1 = -1e30f, l0 = 0.f, l1 = 0.f;
    float o[16][4];
#pragma unroll
    for (int n = 0; n < 16; n++)
#pragma unroll
        for (int r = 0; r < 4; r++) o[n][r] = 0.f;

    const int rowg = q0 + w * 16 + g;
    const int rb = w * 16 + g;

    for (int kc = 0; kc <= qb; kc++) {
        // ---- S = Q @ K^T : warp tile 16 x 128 ----
        float s[16][4];
#pragma unroll
        for (int n = 0; n < 16; n++)
#pragma unroll
            for (int r = 0; r < 4; r++) s[n][r] = 0.f;

#pragma unroll
        for (int kt = 0; kt < 8; kt++) {
            const int kbase = kt * 8 + t;
            uint32_t ah0 = QH[rb * FQ_ST + kbase];
            uint32_t ah1 = QH[(rb + 8) * FQ_ST + kbase];
            uint32_t ah2 = QH[rb * FQ_ST + kbase + 4];
            uint32_t ah3 = QH[(rb + 8) * FQ_ST + kbase + 4];
            uint32_t al0 = QL[rb * FQ_ST + kbase];
            uint32_t al1 = QL[(rb + 8) * FQ_ST + kbase];
            uint32_t al2 = QL[rb * FQ_ST + kbase + 4];
            uint32_t al3 = QL[(rb + 8) * FQ_ST + kbase + 4];
#pragma unroll
            for (int n = 0; n < 16; n++) {
                const int cb = n * 8 + g;
                uint32_t bh0 = KH[cb * FK_ST + kbase];
                uint32_t bh1 = KH[cb * FK_ST + kbase + 4];
                uint32_t bl0 = KL[cb * FK_ST + kbase];
                uint32_t bl1 = KL[cb * FK_ST + kbase + 4];
                mma16(s[n], ah0, ah1, ah2, ah3, bh0, bh1);
                mma16(s[n], ah0, ah1, ah2, ah3, bl0, bl1);
                mma16(s[n], al0, al1, al2, al3, bh0, bh1);
            }
        }

        __syncthreads();                       // K consumed by all warps
        if (kc < qb) {
            fillK(kc + 1);
            asm volatile("cp.async.commit_group;");
        }

        // causal mask on the diagonal tile
        if (kc == qb) {
#pragma unroll
            for (int n = 0; n < 16; n++) {
                int c0 = kc * 128 + n * 8 + 2 * t;
                if (c0 > rowg)          s[n][0] = -1e30f;
                if (c0 + 1 > rowg)      s[n][1] = -1e30f;
                if (c0 > rowg + 8)      s[n][2] = -1e30f;
                if (c0 + 1 > rowg + 8)  s[n][3] = -1e30f;
            }
        }

        // ---- in-warp online softmax ----
        float mx0 = -1e30f, mx1 = -1e30f;
#pragma unroll
        for (int n = 0; n < 16; n++) {
            mx0 = fmaxf(mx0, fmaxf(s[n][0], s[n][1]));
            mx1 = fmaxf(mx1, fmaxf(s[n][2], s[n][3]));
        }
        mx0 = fmaxf(mx0, __shfl_xor_sync(0xffffffffu, mx0, 1));
        mx0 = fmaxf(mx0, __shfl_xor_sync(0xffffffffu, mx0, 2));
        mx1 = fmaxf(mx1, __shfl_xor_sync(0xffffffffu, mx1, 1));
        mx1 = fmaxf(mx1, __shfl_xor_sync(0xffffffffu, mx1, 2));
        float mn0 = fmaxf(m0, mx0), mn1 = fmaxf(m1, mx1);
        float a0 = __expf(m0 - mn0), a1 = __expf(m1 - mn1);
        m0 = mn0; m1 = mn1;
        float rs0 = 0.f, rs1 = 0.f;
#pragma unroll
        for (int n = 0; n < 16; n++) {
            s[n][0] = __expf(s[n][0] - mn0);
            s[n][1] = __expf(s[n][1] - mn0);
            s[n][2] = __expf(s[n][2] - mn1);
            s[n][3] = __expf(s[n][3] - mn1);
            rs0 += s[n][0] + s[n][1];
            rs1 += s[n][2] + s[n][3];
        }
        rs0 += __shfl_xor_sync(0xffffffffu, rs0, 1);
        rs0 += __shfl_xor_sync(0xffffffffu, rs0, 2);
        rs1 += __shfl_xor_sync(0xffffffffu, rs1, 1);
        rs1 += __shfl_xor_sync(0xffffffffu, rs1, 2);
        l0 = l0 * a0 + rs0;
        l1 = l1 * a1 + rs1;
#pragma unroll
        for (int n = 0; n < 16; n++) {
            o[n][0] *= a0; o[n][1] *= a0;
            o[n][2] *= a1; o[n][3] *= a1;
        }

        asm volatile("cp.async.wait_group 1;");  // own V(kc) arrival (K(kc+1) may fly)
        __syncthreads();                          // everyone's V(kc) visible

        // ---- O += P @ V, two kt-halves to bound register pressure ----
#pragma unroll
        for (int half = 0; half < 2; half++) {
            uint32_t phi[4][4], plo[4][4];
#pragma unroll
            for (int q = 0; q < 4; q++) {
                int kt = half * 4 + q;
                pksplit(s[2 * kt][0], s[2 * kt][1], phi[q][0], plo[q][0]);
                pksplit(s[2 * kt][2], s[2 * kt][3], phi[q][1], plo[q][1]);
                pksplit(s[2 * kt + 1][0], s[2 * kt + 1][1], phi[q][2], plo[q][2]);
                pksplit(s[2 * kt + 1][2], s[2 * kt + 1][3], phi[q][3], plo[q][3]);
            }
#pragma unroll
            for (int q = 0; q < 4; q++) {
                const int kb = (half * 4 + q) * 8 + t;
#pragma unroll
                for (int n = 0; n < 16; n++) {
                    const int nb = n * 8 + g;
                    uint32_t bh0 = VH[nb * FV_ST + kb];
                    uint32_t bh1 = VH[nb * FV_ST + kb + 4];
                    uint32_t bl0 = VL[nb * FV_ST + kb];
                    uint32_t bl1 = VL[nb * FV_ST + kb + 4];
                    mma16(o[n], phi[q][0], phi[q][1], phi[q][2], phi[q][3], bh0, bh1);
                    mma16(o[n], phi[q][0], phi[q][1], phi[q][2], phi[q][3], bl0, bl1);
                    mma16(o[n], plo[q][0], plo[q][1], plo[q][2], plo[q][3], bh0, bh1);
                }
            }
        }

        __syncthreads();                       // V consumed by all warps
        if (kc < qb) {
            fillV(kc + 1);
            asm volatile("cp.async.commit_group;");
        }
        asm volatile("cp.async.wait_group 1;");  // own K(kc+1) arrival (V(kc+1) may fly)
        __syncthreads();                          // everyone's K(kc+1) visible
    }

    // epilogue: emit y planes (pairs along d == out-proj K)
    const int row = w * 16 + g;
    float inv0 = 1.f / l0, inv1 = 1.f / l1;
    uint32_t* yh0 = yh + (size_t)(b * SEQ + q0 + row) * 512;
    uint32_t* yl0 = yl + (size_t)(b * SEQ + q0 + row) * 512;
    uint32_t* yh1 = yh + (size_t)(b * SEQ + q0 + row + 8) * 512;
    uint32_t* yl1 = yl + (size_t)(b * SEQ + q0 + row + 8) * 512;
#pragma unroll
    for (int n = 0; n < 16; n++) {
        int cp = hq * 64 + n * 4 + t;
        uint32_t h, l;
        pksplit(o[n][0] * inv0, o[n][1] * inv0, h, l);
        yh0[cp] = h; yl0[cp] = l;
        pksplit(o[n][2] * inv1, o[n][3] * inv1, h, l);
        yh1[cp] = h; yl1[cp] = l;
    }
}

// ---------------- launch ----------------
extern "C" void kernel_launch(void* const* d_in, const int* in_sizes, int n_in,
                              void* d_out, int out_size) {
    const float* x   = (const float*)d_in[0];
    const float* wq  = (const float*)d_in[1];
    const float* wkd = (const float*)d_in[2];
    const float* wvd = (const float*)d_in[3];
    const float* wku = (const float*)d_in[4];
    const float* wvu = (const float*)d_in[5];
    const float* wo  = (const float*)d_in[6];
    float* out = (float*)d_out;

    float* scratch = nullptr;
    cudaGetSymbolAddress((void**)&scratch, g_scratch);
    uint32_t* xh   = (uint32_t*)(scratch + OFF_XH);
    uint32_t* xl   = (uint32_t*)(scratch + OFF_XL);
    uint32_t* wqth = (uint32_t*)(scratch + OFF_WQT_H);
    uint32_t* wqtl = (uint32_t*)(scratch + OFF_WQT_L);
    uint32_t* woth = (uint32_t*)(scratch + OFF_WOT_H);
    uint32_t* wotl = (uint32_t*)(scratch + OFF_WOT_L);
    uint32_t* wkth = (uint32_t*)(scratch + OFF_WKT_H);
    uint32_t* wktl = (uint32_t*)(scratch + OFF_WKT_L);
    uint32_t* qhg  = (uint32_t*)(scratch + OFF_QH);
    uint32_t* qlg  = (uint32_t*)(scratch + OFF_QL);
    uint32_t* kvhg = (uint32_t*)(scratch + OFF_KVH);
    uint32_t* kvlg = (uint32_t*)(scratch + OFF_KVL);
    uint32_t* vthg = (uint32_t*)(scratch + OFF_VTH);
    uint32_t* vtlg = (uint32_t*)(scratch + OFF_VTL);
    uint32_t* yhg  = (uint32_t*)(scratch + OFF_YH);
    uint32_t* ylg  = (uint32_t*)(scratch + OFF_YL);

    const float scale = 0.08838834764831845f;   // 1/sqrt(128)

    // prep: pack operands into split-bf16 planes (scale folded into wq)
    pack_x_kernel<<<8192, 256>>>(x, xh, xl);
    packT_kernel<<<dim3(8, 16), 256>>>(wq, 1024, wqth, wqtl, scale);
    packT_kernel<<<dim3(8, 16), 256>>>(wo, 1024, woth, wotl, 1.0f);
    eff_weightsT_kernel<<<dim3(8, 8), 256>>>(wkd, wvd, wku, wvu, wkth, wktl);

    cudaFuncSetAttribute(mm_proj, cudaFuncAttributeMaxDynamicSharedMemorySize, PP_SMEM);
    cudaFuncSetAttribute(mm_pp_f32, cudaFuncAttributeMaxDynamicSharedMemorySize, PP_SMEM);

    // merged Q + KV projections
    mm_proj<<<dim3(12, 32), 256, PP_SMEM>>>(xh, xl, wqth, wqtl, wkth, wktl,
                                            qhg, qlg, kvhg, kvlg);

    vtrans_kernel<<<dim3(SEQ / 64, N_KV, BATCH), 256>>>(kvhg, kvlg, vthg, vtlg);

    cudaFuncSetAttribute(flash4_kernel, cudaFuncAttributeMaxDynamicSharedMemorySize, FA4_SMEM);
    flash4_kernel<<<dim3(SEQ / 128, N_HEADS, BATCH), 256, FA4_SMEM>>>(qhg, qlg, kvhg, kvlg,
                                                                      vthg, vtlg, yhg, ylg);

    // output projection
    mm_pp_f32<<<dim3(8, 32), 256, PP_SMEM>>>(1024, 1024, yhg, ylg, woth, wotl, out);
}

// round 16
// speedup vs baseline: 1.1293x; 1.0692x over previous
#include <cuda_runtime.h>
#include <cuda_bf16.h>
#include <cstdint>

// Problem constants
#define D_MODEL 1024
#define N_HEADS 8
#define N_KV 2
#define HEAD_DIM 128
#define D_LAT 32
#define BATCH 2
#define SEQ 2048
#define M_TOK (BATCH*SEQ)          // 4096
#define KV_N 512                   // fused K|V width

// ---------------- scratch (4B words) ----------------
#define OFF_XH    0
#define OFF_XL    (OFF_XH   + 4096*512)
#define OFF_WQT_H (OFF_XL   + 4096*512)
#define OFF_WQT_L (OFF_WQT_H + 1024*512)
#define OFF_WOT_H (OFF_WQT_L + 1024*512)
#define OFF_WOT_L (OFF_WOT_H + 1024*512)
#define OFF_WKT_H (OFF_WOT_L + 1024*512)
#define OFF_WKT_L (OFF_WKT_H + 512*512)
#define OFF_QH    (OFF_WKT_L + 512*512)
#define OFF_QL    (OFF_QH   + 4096*512)
#define OFF_KVH   (OFF_QL   + 4096*512)
#define OFF_KVL   (OFF_KVH  + 4096*256)
#define OFF_VTH   (OFF_KVL  + 4096*256)
#define OFF_VTL   (OFF_VTH  + 2*2*128*1024)
#define OFF_YH    (OFF_VTL  + 2*2*128*1024)
#define OFF_YL    (OFF_YH   + 4096*512)
#define SCRATCH_WORDS (OFF_YL + 4096*512)
__device__ float g_scratch[SCRATCH_WORDS];

// ---------------- split-bf16 helpers ----------------
__device__ __forceinline__ void pksplit(float x, float y, uint32_t& hi, uint32_t& lo) {
    __nv_bfloat16 hx = __float2bfloat16(x), hy = __float2bfloat16(y);
    float rx = x - __bfloat162float(hx), ry = y - __bfloat162float(hy);
    hi = ((uint32_t)__bfloat16_as_ushort(hy) << 16) | (uint32_t)__bfloat16_as_ushort(hx);
    lo = ((uint32_t)__bfloat16_as_ushort(__float2bfloat16(ry)) << 16) |
         (uint32_t)__bfloat16_as_ushort(__float2bfloat16(rx));
}
#define HIP(u0,u1) __byte_perm((u0),(u1),0x5410)
#define LOP(u0,u1) __byte_perm((u0),(u1),0x7632)

__device__ __forceinline__ void mma16(float* c, uint32_t a0, uint32_t a1, uint32_t a2, uint32_t a3,
                                      uint32_t b0, uint32_t b1) {
    asm volatile(
        "mma.sync.aligned.m16n8k16.row.col.f32.bf16.bf16.f32 "
        "{%0,%1,%2,%3},{%4,%5,%6,%7},{%8,%9},{%0,%1,%2,%3};"
        : "+f"(c[0]), "+f"(c[1]), "+f"(c[2]), "+f"(c[3])
        : "r"(a0), "r"(a1), "r"(a2), "r"(a3), "r"(b0), "r"(b1));
}

__device__ __forceinline__ void ldsm4(uint32_t& r0, uint32_t& r1, uint32_t& r2, uint32_t& r3,
                                      uint32_t a) {
    asm volatile("ldmatrix.sync.aligned.m8n8.x4.shared.b16 {%0,%1,%2,%3}, [%4];"
                 : "=r"(r0), "=r"(r1), "=r"(r2), "=r"(r3) : "r"(a));
}

__device__ __forceinline__ void cpa16(uint32_t dst_smem, const uint32_t* src) {
    asm volatile("{ .reg .u64 p; cvta.to.global.u64 p, %1; cp.async.ca.shared.global [%0], [p], 16; }"
                 :: "r"(dst_smem), "l"(src));
}

// ---------------- prep: pack x into hi/lo planes (pairs along K) ----------------
__global__ void pack_x_kernel(const float* __restrict__ x,
                              uint32_t* __restrict__ xh, uint32_t* __restrict__ xl) {
    int idx = blockIdx.x * blockDim.x + threadIdx.x;    // 4096*512
    float2 v = *(const float2*)(x + 2 * (size_t)idx);
    uint32_t h, l;
    pksplit(v.x, v.y, h, l);
    xh[idx] = h; xl[idx] = l;
}

// ---------------- prep: transpose-pack weight [1024][N] -> planes [N][512], scale folded ----------------
__global__ __launch_bounds__(256) void packT_kernel(const float* __restrict__ w, int N,
                                                    uint32_t* __restrict__ th,
                                                    uint32_t* __restrict__ tl,
                                                    float scale) {
    __shared__ uint32_t sh[64][65];
    __shared__ uint32_t sl[64][65];
    const int kp0 = blockIdx.x * 64;   // kpair base (kpair < 512)
    const int n0 = blockIdx.y * 64;
    const int tid = threadIdx.x;
#pragma unroll
    for (int i = 0; i < 16; i++) {
        int idx = i * 256 + tid;
        int kp = idx >> 6, n = idx & 63;
        float a = w[(size_t)(2 * (kp0 + kp)) * N + n0 + n] * scale;
        float b = w[(size_t)(2 * (kp0 + kp) + 1) * N + n0 + n] * scale;
        uint32_t h, l;
        pksplit(a, b, h, l);
        sh[kp][n] = h; sl[kp][n] = l;
    }
    __syncthreads();
#pragma unroll
    for (int i = 0; i < 16; i++) {
        int idx = i * 256 + tid;
        int n = idx >> 6, kp = idx & 63;
        th[(size_t)(n0 + n) * 512 + kp0 + kp] = sh[kp][n];
        tl[(size_t)(n0 + n) * 512 + kp0 + kp] = sl[kp][n];
    }
}

// ---------------- prep: effective KV weights, transposed planes [512][512] ----------------
__global__ __launch_bounds__(256) void eff_weightsT_kernel(const float* __restrict__ wkd,
                                                           const float* __restrict__ wvd,
                                                           const float* __restrict__ wku,
                                                           const float* __restrict__ wvu,
                                                           uint32_t* __restrict__ th,
                                                           uint32_t* __restrict__ tl) {
    __shared__ float su[32][64];       // wu[l][d0+dd]
    __shared__ float swd[128][33];     // wd[cbase+r][h*32+l]
    const int c0b = blockIdx.x * 64;   // c0 pair base
    const int n0  = blockIdx.y * 64;   // output row base
    const int which = n0 >> 8;
    const int h = (n0 >> 7) & 1;
    const int d0 = n0 & 127;
    const float* wd = which ? wvd : wkd;
    const float* wu = which ? wvu : wku;
    const int tid = threadIdx.x;

#pragma unroll
    for (int i = 0; i < 8; i++) {
        int idx = i * 256 + tid;
        int l = idx >> 6, dd = idx & 63;
        su[l][dd] = wu[l * HEAD_DIM + d0 + dd];
    }
#pragma unroll
    for (int i = 0; i < 16; i++) {
        int idx = i * 256 + tid;
        int r = idx >> 5, l = idx & 31;
        swd[r][l] = wd[(size_t)(2 * c0b + r) * (N_KV * D_LAT) + h * D_LAT + l];
    }
    __syncthreads();

    const int c0l = tid & 63;
    const int nb = tid >> 6;
#pragma unroll
    for (int i = 0; i < 16; i++) {
        int nn = nb * 16 + i;
        float s0 = 0.f, s1 = 0.f;
#pragma unroll
        for (int l = 0; l < 32; l++) {
            float u = su[l][nn];
            s0 += swd[2 * c0l][l] * u;
            s1 += swd[2 * c0l + 1][l] * u;
        }
        uint32_t hi, lo;
        pksplit(s0, s1, hi, lo);
        th[(size_t)(n0 + nn) * 512 + c0b + c0l] = hi;
        tl[(size_t)(n0 + nn) * 512 + c0b + c0l] = lo;
    }
}

// ---------------- pre-packed plane GEMM core (ldmatrix fragments) ----------------
#define PP_ST 20
#define PP_A (128*PP_ST)
#define PP_BUF (2*PP_A)
#define SM_PA 0
#define SM_PB (2*PP_BUF)
#define PP_SMEM (4*PP_BUF*4)    // 81920 bytes

#define PP_MAIN(Ah, Al, Bh, Bl, K, COL0)                                                    \
    extern __shared__ uint32_t sm[];                                                         \
    const uint32_t smb = (uint32_t)__cvta_generic_to_shared(sm);                             \
    const int tid = threadIdx.x;                                                             \
    const int w = tid >> 5;                                                                  \
    const int wm = w & 1;                                                                    \
    const int wn = w >> 1;                                                                   \
    const int lane = tid & 31;                                                               \
    const int g = lane >> 2;                                                                 \
    const int t = lane & 3;                                                                  \
    const int lane15 = lane & 15;                                                            \
    const int l7 = lane & 7;                                                                 \
    const int kAsel = (lane >> 4) * 4;                                                       \
    const int kBsel = ((lane >> 3) & 1) * 4;                                                 \
    const int nBsel = (lane >> 4) & 1;                                                       \
    const int row0 = blockIdx.y * 128;                                                       \
    const int col0 = (COL0);                                                                 \
    const int kph = (K) >> 1;                                                                \
    auto fill = [&](int tt, int buf) {                                                       \
        const int kp0 = tt * 16;                                                             \
        _Pragma("unroll")                                                                    \
        for (int i = 0; i < 4; i++) {                                                        \
            int idx = i * 256 + tid;                                                         \
            int plane = idx >> 9;                                                            \
            int r = (idx >> 2) & 127;                                                        \
            int ch = (idx & 3) << 2;                                                         \
            const uint32_t* sa = (plane ? Al : Ah) + (size_t)(row0 + r) * kph + kp0 + ch;    \
            cpa16(smb + (SM_PA + buf * PP_BUF + plane * PP_A + r * PP_ST + ch) * 4, sa);     \
            const uint32_t* sb = (plane ? Bl : Bh) + (size_t)(col0 + r) * kph + kp0 + ch;    \
            cpa16(smb + (SM_PB + buf * PP_BUF + plane * PP_A + r * PP_ST + ch) * 4, sb);     \
        }                                                                                    \
    };                                                                                       \
    float c[4][4][4];                                                                        \
    _Pragma("unroll")                                                                        \
    for (int i = 0; i < 4; i++)                                                              \
        _Pragma("unroll")                                                                    \
        for (int j = 0; j < 4; j++)                                                          \
            _Pragma("unroll")                                                                \
            for (int r = 0; r < 4; r++) c[i][j][r] = 0.f;                                    \
    const int nt = (K) >> 5;                                                                 \
    fill(0, 0);                                                                              \
    asm volatile("cp.async.commit_group;");                                                  \
    asm volatile("cp.async.wait_group 0;");                                                  \
    __syncthreads();                                                                         \
    for (int tt = 0; tt < nt; tt++) {                                                        \
        if (tt + 1 < nt) {                                                                   \
            fill(tt + 1, (tt + 1) & 1);                                                      \
            asm volatile("cp.async.commit_group;");                                          \
        }                                                                                    \
        const uint32_t aBase = SM_PA + (tt & 1) * PP_BUF;                                    \
        const uint32_t bBase = SM_PB + (tt & 1) * PP_BUF;                                    \
        _Pragma("unroll")                                                                    \
        for (int kk = 0; kk < 2; kk++) {                                                     \
            const int kb8 = kk * 8;                                                          \
            uint32_t ah[4][4], al[4][4], bh[2][4], bl[2][4];                                 \
            _Pragma("unroll")                                                                \
            for (int i = 0; i < 4; i++) {                                                    \
                uint32_t offA = (uint32_t)((wm * 64 + i * 16 + lane15) * PP_ST + kb8 + kAsel); \
                ldsm4(ah[i][0], ah[i][1], ah[i][2], ah[i][3], smb + (aBase + offA) * 4);     \
                ldsm4(al[i][0], al[i][1], al[i][2], al[i][3], smb + (aBase + PP_A + offA) * 4); \
            }                                                                                \
            _Pragma("unroll")                                                                \
            for (int jp = 0; jp < 2; jp++) {                                                 \
                uint32_t offB = (uint32_t)((wn * 32 + jp * 16 + nBsel * 8 + l7) * PP_ST + kb8 + kBsel); \
                ldsm4(bh[jp][0], bh[jp][1], bh[jp][2], bh[jp][3], smb + (bBase + offB) * 4); \
                ldsm4(bl[jp][0], bl[jp][1], bl[jp][2], bl[jp][3], smb + (bBase + PP_A + offB) * 4); \
            }                                                                                \
            _Pragma("unroll")                                                                \
            for (int i = 0; i < 4; i++)                                                      \
                _Pragma("unroll")                                                            \
                for (int j = 0; j < 4; j++) {                                                \
                    const int jp = j >> 1;                                                   \
                    const int sb2 = (j & 1) * 2;                                             \
                    mma16(c[i][j], ah[i][0], ah[i][1], ah[i][2], ah[i][3], bh[jp][sb2], bh[jp][sb2 + 1]); \
                    mma16(c[i][j], ah[i][0], ah[i][1], ah[i][2], ah[i][3], bl[jp][sb2], bl[jp][sb2 + 1]); \
                    mma16(c[i][j], al[i][0], al[i][1], al[i][2], al[i][3], bh[jp][sb2], bh[jp][sb2 + 1]); \
                }                                                                            \
        }                                                                                    \
        if (tt + 1 < nt) {                                                                   \
            asm volatile("cp.async.wait_group 0;");                                          \
            __syncthreads();                                                                 \
        }                                                                                    \
    }

// merged Q + KV projection (plane output). grid (12, 32): bx<8 -> Q, else KV.
__global__ __launch_bounds__(256) void mm_proj(const uint32_t* __restrict__ Ah,
                                               const uint32_t* __restrict__ Al,
                                               const uint32_t* __restrict__ wqh,
                                               const uint32_t* __restrict__ wql,
                                               const uint32_t* __restrict__ wkh,
                                               const uint32_t* __restrict__ wkl,
                                               uint32_t* __restrict__ qh,
                                               uint32_t* __restrict__ ql,
                                               uint32_t* __restrict__ kvh,
                                               uint32_t* __restrict__ kvl) {
    const bool isq = blockIdx.x < 8;
    const uint32_t* Bh = isq ? wqh : wkh;
    const uint32_t* Bl = isq ? wql : wkl;
    uint32_t* Ph = isq ? qh : kvh;
    uint32_t* Pl = isq ? ql : kvl;
    const int np = isq ? 512 : 256;
    PP_MAIN(Ah, Al, Bh, Bl, 1024, (isq ? blockIdx.x : blockIdx.x - 8) * 128)
#pragma unroll
    for (int i = 0; i < 4; i++) {
        int r = row0 + wm * 64 + i * 16 + g;
#pragma unroll
        for (int j = 0; j < 4; j++) {
            int cp = (col0 + wn * 32 + j * 8 + t * 2) >> 1;
            uint32_t h0, l0, h1, l1;
            pksplit(c[i][j][0], c[i][j][1], h0, l0);
            pksplit(c[i][j][2], c[i][j][3], h1, l1);
            Ph[(size_t)r * np + cp] = h0;
            Pl[(size_t)r * np + cp] = l0;
            Ph[(size_t)(r + 8) * np + cp] = h1;
            Pl[(size_t)(r + 8) * np + cp] = l1;
        }
    }
}

// fp32-output variant (out projection)
__global__ __launch_bounds__(256) void mm_pp_f32(int N, int K,
                                                 const uint32_t* __restrict__ Ah,
                                                 const uint32_t* __restrict__ Al,
                                                 const uint32_t* __restrict__ Bh,
                                                 const uint32_t* __restrict__ Bl,
                                                 float* __restrict__ C) {
    PP_MAIN(Ah, Al, Bh, Bl, K, blockIdx.x * 128)
#pragma unroll
    for (int i = 0; i < 4; i++) {
        int r = row0 + wm * 64 + i * 16 + g;
#pragma unroll
        for (int j = 0; j < 4; j++) {
            int cc = col0 + wn * 32 + j * 8 + t * 2;
            *(float2*)(C + (size_t)r * N + cc) = make_float2(c[i][j][0], c[i][j][1]);
            *(float2*)(C + (size_t)(r + 8) * N + cc) = make_float2(c[i][j][2], c[i][j][3]);
        }
    }
}

// ---------------- V transpose: KV planes [token][dpair] -> VT planes [d][tokenpair] ----------------
__global__ __launch_bounds__(256) void vtrans_kernel(const uint32_t* __restrict__ kvh,
                                                     const uint32_t* __restrict__ kvl,
                                                     uint32_t* __restrict__ vth,
                                                     uint32_t* __restrict__ vtl) {
    __shared__ uint32_t tile[64][65];
    const int t0 = blockIdx.x * 64;
    const int kvhd = blockIdx.y;
    const int b = blockIdx.z;
    const int tid = threadIdx.x;
#pragma unroll
    for (int p = 0; p < 2; p++) {
        const uint32_t* src = p ? kvl : kvh;
        uint32_t* dst = p ? vtl : vth;
#pragma unroll
        for (int i = 0; i < 16; i++) {
            int idx = i * 256 + tid;
            int r = idx >> 6, cx = idx & 63;
            tile[r][cx] = src[(size_t)(b * SEQ + t0 + r) * 256 + 128 + kvhd * 64 + cx];
        }
        __syncthreads();
#pragma unroll
        for (int i = 0; i < 16; i++) {
            int idx = i * 256 + tid;
            int d = idx >> 5, tpl = idx & 31;
            uint32_t u0 = tile[2 * tpl][d >> 1];
            uint32_t u1 = tile[2 * tpl + 1][d >> 1];
            uint32_t res = (d & 1) ? LOP(u0, u1) : HIP(u0, u1);
            dst[(size_t)((b * N_KV + kvhd) * 128 + d) * 1024 + (t0 >> 1) + tpl] = res;
        }
        __syncthreads();
    }
}

// ---------------- flash attention v5: ldmatrix fragments, BC=128, pipelined fills ----------------
#define FQ_ST 68
#define FK_ST 68
#define FV_ST 68
#define SM4_QH 0
#define SM4_QL (128*FQ_ST)
#define SM4_K  (2*128*FQ_ST)
#define SM4_V  (SM4_K + 2*128*FK_ST)
#define FA4_SMEM ((SM4_V + 2*128*FV_ST)*4)     // 208896 bytes

__global__ __launch_bounds__(256, 1) void flash5_kernel(const uint32_t* __restrict__ qh,
                                                        const uint32_t* __restrict__ ql,
                                                        const uint32_t* __restrict__ kvh,
                                                        const uint32_t* __restrict__ kvl,
                                                        const uint32_t* __restrict__ vth,
                                                        const uint32_t* __restrict__ vtl,
                                                        uint32_t* __restrict__ yh,
                                                        uint32_t* __restrict__ yl) {
    extern __shared__ uint32_t sm[];
    const uint32_t smb = (uint32_t)__cvta_generic_to_shared(sm);

    const int qb = (SEQ / 128 - 1) - blockIdx.x;   // heavy tiles first
    const int hq = blockIdx.y;
    const int b  = blockIdx.z;
    const int kvhd = hq >> 2;
    const int tid = threadIdx.x;
    const int w = tid >> 5;
    const int lane = tid & 31;
    const int g = lane >> 2;
    const int t = lane & 3;
    const int lane15 = lane & 15;
    const int l7 = lane & 7;
    const int kAsel = (lane >> 4) * 4;
    const int kBsel = ((lane >> 3) & 1) * 4;
    const int nBsel = (lane >> 4) & 1;
    const int q0 = qb * 128;

    // ---- prologue fills ----
#pragma unroll
    for (int i = 0; i < 16; i++) {
        int idx = i * 256 + tid;
        int plane = idx >> 11;
        int r = (idx >> 4) & 127;
        int ch = (idx & 15) << 2;
        const uint32_t* src = (plane ? ql : qh) + (size_t)(b * SEQ + q0 + r) * 512 + hq * 64 + ch;
        cpa16(smb + (SM4_QH + plane * (128 * FQ_ST) + r * FQ_ST + ch) * 4, src);
    }
    auto fillK = [&](int kt) {
#pragma unroll
        for (int i = 0; i < 16; i++) {
            int idx = i * 256 + tid;
            int plane = idx >> 11;
            int r = (idx >> 4) & 127;
            int ch = (idx & 15) << 2;
            const uint32_t* src = (plane ? kvl : kvh) +
                                  (size_t)(b * SEQ + kt * 128 + r) * 256 + kvhd * 64 + ch;
            cpa16(smb + (SM4_K + plane * (128 * FK_ST) + r * FK_ST + ch) * 4, src);
        }
    };
    auto fillV = [&](int kt) {
#pragma unroll
        for (int i = 0; i < 16; i++) {
            int idx = i * 256 + tid;
            int plane = idx >> 11;
            int d = (idx >> 4) & 127;
            int ch = (idx & 15) << 2;
            const uint32_t* src = (plane ? vtl : vth) +
                                  (size_t)((b * N_KV + kvhd) * 128 + d) * 1024 + kt * 64 + ch;
            cpa16(smb + (SM4_V + plane * (128 * FV_ST) + d * FV_ST + ch) * 4, src);
        }
    };
    fillK(0);
    fillV(0);
    asm volatile("cp.async.commit_group;");
    asm volatile("cp.async.wait_group 0;");
    __syncthreads();

    float m0 = -1e30f, m1 = -1e30f, l0 = 0.f, l1 = 0.f;
    float o[16][4];
#pragma unroll
    for (int n = 0; n < 16; n++)
#pragma unroll
        for (int r = 0; r < 4; r++) o[n][r] = 0.f;

    const int rowg = q0 + w * 16 + g;
    const int rb0 = w * 16;

    for (int kc = 0; kc <= qb; kc++) {
        // ---- S = Q @ K^T : warp tile 16 x 128 (ldmatrix fragments) ----
        float s[16][4];
#pragma unroll
        for (int n = 0; n < 16; n++)
#pragma unroll
            for (int r = 0; r < 4; r++) s[n][r] = 0.f;

#pragma unroll
        for (int kt = 0; kt < 8; kt++) {
            uint32_t ah[4], al[4];
            const uint32_t offQ = (uint32_t)((rb0 + lane15) * FQ_ST + kt * 8 + kAsel);
            ldsm4(ah[0], ah[1], ah[2], ah[3], smb + (SM4_QH + offQ) * 4);
            ldsm4(al[0], al[1], al[2], al[3], smb + (SM4_QL + offQ) * 4);
#pragma unroll
            for (int np = 0; np < 8; np++) {
                uint32_t bh[4], bl[4];
                const uint32_t offK = (uint32_t)((np * 16 + nBsel * 8 + l7) * FK_ST + kt * 8 + kBsel);
                ldsm4(bh[0], bh[1], bh[2], bh[3], smb + (SM4_K + offK) * 4);
                ldsm4(bl[0], bl[1], bl[2], bl[3], smb + (SM4_K + 128 * FK_ST + offK) * 4);
                mma16(s[2 * np],     ah[0], ah[1], ah[2], ah[3], bh[0], bh[1]);
                mma16(s[2 * np],     ah[0], ah[1], ah[2], ah[3], bl[0], bl[1]);
                mma16(s[2 * np],     al[0], al[1], al[2], al[3], bh[0], bh[1]);
                mma16(s[2 * np + 1], ah[0], ah[1], ah[2], ah[3], bh[2], bh[3]);
                mma16(s[2 * np + 1], ah[0], ah[1], ah[2], ah[3], bl[2], bl[3]);
                mma16(s[2 * np + 1], al[0], al[1], al[2], al[3], bh[2], bh[3]);
            }
        }

        __syncthreads();                       // K consumed by all warps
        if (kc < qb) {
            fillK(kc + 1);
            asm volatile("cp.async.commit_group;");
        }

        // causal mask on the diagonal tile
        if (kc == qb) {
#pragma unroll
            for (int n = 0; n < 16; n++) {
                int c0 = kc * 128 + n * 8 + 2 * t;
                if (c0 > rowg)          s[n][0] = -1e30f;
                if (c0 + 1 > rowg)      s[n][1] = -1e30f;
                if (c0 > rowg + 8)      s[n][2] = -1e30f;
                if (c0 + 1 > rowg + 8)  s[n][3] = -1e30f;
            }
        }

        // ---- in-warp online softmax ----
        float mx0 = -1e30f, mx1 = -1e30f;
#pragma unroll
        for (int n = 0; n < 16; n++) {
            mx0 = fmaxf(mx0, fmaxf(s[n][0], s[n][1]));
            mx1 = fmaxf(mx1, fmaxf(s[n][2], s[n][3]));
        }
        mx0 = fmaxf(mx0, __shfl_xor_sync(0xffffffffu, mx0, 1));
        mx0 = fmaxf(mx0, __shfl_xor_sync(0xffffffffu, mx0, 2));
        mx1 = fmaxf(mx1, __shfl_xor_sync(0xffffffffu, mx1, 1));
        mx1 = fmaxf(mx1, __shfl_xor_sync(0xffffffffu, mx1, 2));
        float mn0 = fmaxf(m0, mx0), mn1 = fmaxf(m1, mx1);
        float a0 = __expf(m0 - mn0), a1 = __expf(m1 - mn1);
        m0 = mn0; m1 = mn1;
        float rs0 = 0.f, rs1 = 0.f;
#pragma unroll
        for (int n = 0; n < 16; n++) {
            s[n][0] = __expf(s[n][0] - mn0);
            s[n][1] = __expf(s[n][1] - mn0);
            s[n][2] = __expf(s[n][2] - mn1);
            s[n][3] = __expf(s[n][3] - mn1);
            rs0 += s[n][0] + s[n][1];
            rs1 += s[n][2] + s[n][3];
        }
        rs0 += __shfl_xor_sync(0xffffffffu, rs0, 1);
        rs0 += __shfl_xor_sync(0xffffffffu, rs0, 2);
        rs1 += __shfl_xor_sync(0xffffffffu, rs1, 1);
        rs1 += __shfl_xor_sync(0xffffffffu, rs1, 2);
        l0 = l0 * a0 + rs0;
        l1 = l1 * a1 + rs1;
#pragma unroll
        for (int n = 0; n < 16; n++) {
            o[n][0] *= a0; o[n][1] *= a0;
            o[n][2] *= a1; o[n][3] *= a1;
        }

        asm volatile("cp.async.wait_group 1;");  // own V(kc) arrival (K(kc+1) may fly)
        __syncthreads();                          // everyone's V(kc) visible

        // ---- O += P @ V, two kt-halves (ldmatrix B fragments) ----
#pragma unroll
        for (int half = 0; half < 2; half++) {
            uint32_t phi[4][4], plo[4][4];
#pragma unroll
            for (int q = 0; q < 4; q++) {
                int kt = half * 4 + q;
                pksplit(s[2 * kt][0], s[2 * kt][1], phi[q][0], plo[q][0]);
                pksplit(s[2 * kt][2], s[2 * kt][3], phi[q][1], plo[q][1]);
                pksplit(s[2 * kt + 1][0], s[2 * kt + 1][1], phi[q][2], plo[q][2]);
                pksplit(s[2 * kt + 1][2], s[2 * kt + 1][3], phi[q][3], plo[q][3]);
            }
#pragma unroll
            for (int q = 0; q < 4; q++) {
                const int koff = (half * 4 + q) * 8 + kBsel;
#pragma unroll
                for (int np = 0; np < 8; np++) {
                    uint32_t vh[4], vl[4];
                    const uint32_t offV = (uint32_t)((np * 16 + nBsel * 8 + l7) * FV_ST + koff);
                    ldsm4(vh[0], vh[1], vh[2], vh[3], smb + (SM4_V + offV) * 4);
                    ldsm4(vl[0], vl[1], vl[2], vl[3], smb + (SM4_V + 128 * FV_ST + offV) * 4);
                    mma16(o[2 * np],     phi[q][0], phi[q][1], phi[q][2], phi[q][3], vh[0], vh[1]);
                    mma16(o[2 * np],     phi[q][0], phi[q][1], phi[q][2], phi[q][3], vl[0], vl[1]);
                    mma16(o[2 * np],     plo[q][0], plo[q][1], plo[q][2], plo[q][3], vh[0], vh[1]);
                    mma16(o[2 * np + 1], phi[q][0], phi[q][1], phi[q][2], phi[q][3], vh[2], vh[3]);
                    mma16(o[2 * np + 1], phi[q][0], phi[q][1], phi[q][2], phi[q][3], vl[2], vl[3]);
                    mma16(o[2 * np + 1], plo[q][0], plo[q][1], plo[q][2], plo[q][3], vh[2], vh[3]);
                }
            }
        }

        __syncthreads();                       // V consumed by all warps
        if (kc < qb) {
            fillV(kc + 1);
            asm volatile("cp.async.commit_group;");
        }
        asm volatile("cp.async.wait_group 1;");  // own K(kc+1) arrival (V(kc+1) may fly)
        __syncthreads();                          // everyone's K(kc+1) visible
    }

    // epilogue: emit y planes (pairs along d == out-proj K)
    const int row = w * 16 + g;
    float inv0 = 1.f / l0, inv1 = 1.f / l1;
    uint32_t* yh0 = yh + (size_t)(b * SEQ + q0 + row) * 512;
    uint32_t* yl0 = yl + (size_t)(b * SEQ + q0 + row) * 512;
    uint32_t* yh1 = yh + (size_t)(b * SEQ + q0 + row + 8) * 512;
    uint32_t* yl1 = yl + (size_t)(b * SEQ + q0 + row + 8) * 512;
#pragma unroll
    for (int n = 0; n < 16; n++) {
        int cp = hq * 64 + n * 4 + t;
        uint32_t h, l;
        pksplit(o[n][0] * inv0, o[n][1] * inv0, h, l);
        yh0[cp] = h; yl0[cp] = l;
        pksplit(o[n][2] * inv1, o[n][3] * inv1, h, l);
        yh1[cp] = h; yl1[cp] = l;
    }
}

// ---------------- launch ----------------
extern "C" void kernel_launch(void* const* d_in, const int* in_sizes, int n_in,
                              void* d_out, int out_size) {
    const float* x   = (const float*)d_in[0];
    const float* wq  = (const float*)d_in[1];
    const float* wkd = (const float*)d_in[2];
    const float* wvd = (const float*)d_in[3];
    const float* wku = (const float*)d_in[4];
    const float* wvu = (const float*)d_in[5];
    const float* wo  = (const float*)d_in[6];
    float* out = (float*)d_out;

    float* scratch = nullptr;
    cudaGetSymbolAddress((void**)&scratch, g_scratch);
    uint32_t* xh   = (uint32_t*)(scratch + OFF_XH);
    uint32_t* xl   = (uint32_t*)(scratch + OFF_XL);
    uint32_t* wqth = (uint32_t*)(scratch + OFF_WQT_H);
    uint32_t* wqtl = (uint32_t*)(scratch + OFF_WQT_L);
    uint32_t* woth = (uint32_t*)(scratch + OFF_WOT_H);
    uint32_t* wotl = (uint32_t*)(scratch + OFF_WOT_L);
    uint32_t* wkth = (uint32_t*)(scratch + OFF_WKT_H);
    uint32_t* wktl = (uint32_t*)(scratch + OFF_WKT_L);
    uint32_t* qhg  = (uint32_t*)(scratch + OFF_QH);
    uint32_t* qlg  = (uint32_t*)(scratch + OFF_QL);
    uint32_t* kvhg = (uint32_t*)(scratch + OFF_KVH);
    uint32_t* kvlg = (uint32_t*)(scratch + OFF_KVL);
    uint32_t* vthg = (uint32_t*)(scratch + OFF_VTH);
    uint32_t* vtlg = (uint32_t*)(scratch + OFF_VTL);
    uint32_t* yhg  = (uint32_t*)(scratch + OFF_YH);
    uint32_t* ylg  = (uint32_t*)(scratch + OFF_YL);

    const float scale = 0.08838834764831845f;   // 1/sqrt(128)

    // prep: pack operands into split-bf16 planes (scale folded into wq)
    pack_x_kernel<<<8192, 256>>>(x, xh, xl);
    packT_kernel<<<dim3(8, 16), 256>>>(wq, 1024, wqth, wqtl, scale);
    packT_kernel<<<dim3(8, 16), 256>>>(wo, 1024, woth, wotl, 1.0f);
    eff_weightsT_kernel<<<dim3(8, 8), 256>>>(wkd, wvd, wku, wvu, wkth, wktl);

    cudaFuncSetAttribute(mm_proj, cudaFuncAttributeMaxDynamicSharedMemorySize, PP_SMEM);
    cudaFuncSetAttribute(mm_pp_f32, cudaFuncAttributeMaxDynamicSharedMemorySize, PP_SMEM);

    // merged Q + KV projections
    mm_proj<<<dim3(12, 32), 256, PP_SMEM>>>(xh, xl, wqth, wqtl, wkth, wktl,
                                            qhg, qlg, kvhg, kvlg);

    vtrans_kernel<<<dim3(SEQ / 64, N_KV, BATCH), 256>>>(kvhg, kvlg, vthg, vtlg);

    cudaFuncSetAttribute(flash5_kernel, cudaFuncAttributeMaxDynamicSharedMemorySize, FA4_SMEM);
    flash5_kernel<<<dim3(SEQ / 128, N_HEADS, BATCH), 256, FA4_SMEM>>>(qhg, qlg, kvhg, kvlg,
                                                                      vthg, vtlg, yhg, ylg);

    // output projection
    mm_pp_f32<<<dim3(8, 32), 256, PP_SMEM>>>(1024, 1024, yhg, ylg, woth, wotl, out);
}

// round 17
// speedup vs baseline: 1.1342x; 1.0043x over previous
#include <cuda_runtime.h>
#include <cuda_bf16.h>
#include <cstdint>

// Problem constants
#define D_MODEL 1024
#define N_HEADS 8
#define N_KV 2
#define HEAD_DIM 128
#define D_LAT 32
#define BATCH 2
#define SEQ 2048
#define M_TOK (BATCH*SEQ)          // 4096
#define KV_N 512                   // fused K|V width

// ---------------- scratch (4B words) ----------------
#define OFF_XH    0
#define OFF_XL    (OFF_XH   + 4096*512)
#define OFF_WQT_H (OFF_XL   + 4096*512)
#define OFF_WQT_L (OFF_WQT_H + 1024*512)
#define OFF_WOT_H (OFF_WQT_L + 1024*512)
#define OFF_WOT_L (OFF_WOT_H + 1024*512)
#define OFF_WKT_H (OFF_WOT_L + 1024*512)
#define OFF_WKT_L (OFF_WKT_H + 512*512)
#define OFF_QH    (OFF_WKT_L + 512*512)
#define OFF_QL    (OFF_QH   + 4096*512)
#define OFF_KVH   (OFF_QL   + 4096*512)
#define OFF_KVL   (OFF_KVH  + 4096*256)
#define OFF_VTH   (OFF_KVL  + 4096*256)
#define OFF_VTL   (OFF_VTH  + 2*2*128*1024)
#define OFF_YH    (OFF_VTL  + 2*2*128*1024)
#define OFF_YL    (OFF_YH   + 4096*512)
#define SCRATCH_WORDS (OFF_YL + 4096*512)
__device__ float g_scratch[SCRATCH_WORDS];

// ---------------- split-bf16 helpers ----------------
__device__ __forceinline__ void pksplit(float x, float y, uint32_t& hi, uint32_t& lo) {
    __nv_bfloat16 hx = __float2bfloat16(x), hy = __float2bfloat16(y);
    float rx = x - __bfloat162float(hx), ry = y - __bfloat162float(hy);
    hi = ((uint32_t)__bfloat16_as_ushort(hy) << 16) | (uint32_t)__bfloat16_as_ushort(hx);
    lo = ((uint32_t)__bfloat16_as_ushort(__float2bfloat16(ry)) << 16) |
         (uint32_t)__bfloat16_as_ushort(__float2bfloat16(rx));
}
#define HIP(u0,u1) __byte_perm((u0),(u1),0x5410)
#define LOP(u0,u1) __byte_perm((u0),(u1),0x7632)

__device__ __forceinline__ void mma16(float* c, uint32_t a0, uint32_t a1, uint32_t a2, uint32_t a3,
                                      uint32_t b0, uint32_t b1) {
    asm volatile(
        "mma.sync.aligned.m16n8k16.row.col.f32.bf16.bf16.f32 "
        "{%0,%1,%2,%3},{%4,%5,%6,%7},{%8,%9},{%0,%1,%2,%3};"
        : "+f"(c[0]), "+f"(c[1]), "+f"(c[2]), "+f"(c[3])
        : "r"(a0), "r"(a1), "r"(a2), "r"(a3), "r"(b0), "r"(b1));
}

__device__ __forceinline__ void ldsm4(uint32_t& r0, uint32_t& r1, uint32_t& r2, uint32_t& r3,
                                      uint32_t a) {
    asm volatile("ldmatrix.sync.aligned.m8n8.x4.shared.b16 {%0,%1,%2,%3}, [%4];"
                 : "=r"(r0), "=r"(r1), "=r"(r2), "=r"(r3) : "r"(a));
}

__device__ __forceinline__ void cpa16(uint32_t dst_smem, const uint32_t* src) {
    asm volatile("{ .reg .u64 p; cvta.to.global.u64 p, %1; cp.async.ca.shared.global [%0], [p], 16; }"
                 :: "r"(dst_smem), "l"(src));
}

// ---------------- prep: pack x into hi/lo planes (pairs along K) ----------------
__global__ void pack_x_kernel(const float* __restrict__ x,
                              uint32_t* __restrict__ xh, uint32_t* __restrict__ xl) {
    int idx = blockIdx.x * blockDim.x + threadIdx.x;    // 4096*512
    float2 v = *(const float2*)(x + 2 * (size_t)idx);
    uint32_t h, l;
    pksplit(v.x, v.y, h, l);
    xh[idx] = h; xl[idx] = l;
}

// ---------------- prep: transpose-pack weight [1024][N] -> planes [N][512], scale folded ----------------
__global__ __launch_bounds__(256) void packT_kernel(const float* __restrict__ w, int N,
                                                    uint32_t* __restrict__ th,
                                                    uint32_t* __restrict__ tl,
                                                    float scale) {
    __shared__ uint32_t sh[64][65];
    __shared__ uint32_t sl[64][65];
    const int kp0 = blockIdx.x * 64;   // kpair base (kpair < 512)
    const int n0 = blockIdx.y * 64;
    const int tid = threadIdx.x;
#pragma unroll
    for (int i = 0; i < 16; i++) {
        int idx = i * 256 + tid;
        int kp = idx >> 6, n = idx & 63;
        float a = w[(size_t)(2 * (kp0 + kp)) * N + n0 + n] * scale;
        float b = w[(size_t)(2 * (kp0 + kp) + 1) * N + n0 + n] * scale;
        uint32_t h, l;
        pksplit(a, b, h, l);
        sh[kp][n] = h; sl[kp][n] = l;
    }
    __syncthreads();
#pragma unroll
    for (int i = 0; i < 16; i++) {
        int idx = i * 256 + tid;
        int n = idx >> 6, kp = idx & 63;
        th[(size_t)(n0 + n) * 512 + kp0 + kp] = sh[kp][n];
        tl[(size_t)(n0 + n) * 512 + kp0 + kp] = sl[kp][n];
    }
}

// ---------------- prep: effective KV weights, transposed planes [512][512] ----------------
__global__ __launch_bounds__(256) void eff_weightsT_kernel(const float* __restrict__ wkd,
                                                           const float* __restrict__ wvd,
                                                           const float* __restrict__ wku,
                                                           const float* __restrict__ wvu,
                                                           uint32_t* __restrict__ th,
                                                           uint32_t* __restrict__ tl) {
    __shared__ float su[32][64];       // wu[l][d0+dd]
    __shared__ float swd[128][33];     // wd[cbase+r][h*32+l]
    const int c0b = blockIdx.x * 64;   // c0 pair base
    const int n0  = blockIdx.y * 64;   // output row base
    const int which = n0 >> 8;
    const int h = (n0 >> 7) & 1;
    const int d0 = n0 & 127;
    const float* wd = which ? wvd : wkd;
    const float* wu = which ? wvu : wku;
    const int tid = threadIdx.x;

#pragma unroll
    for (int i = 0; i < 8; i++) {
        int idx = i * 256 + tid;
        int l = idx >> 6, dd = idx & 63;
        su[l][dd] = wu[l * HEAD_DIM + d0 + dd];
    }
#pragma unroll
    for (int i = 0; i < 16; i++) {
        int idx = i * 256 + tid;
        int r = idx >> 5, l = idx & 31;
        swd[r][l] = wd[(size_t)(2 * c0b + r) * (N_KV * D_LAT) + h * D_LAT + l];
    }
    __syncthreads();

    const int c0l = tid & 63;
    const int nb = tid >> 6;
#pragma unroll
    for (int i = 0; i < 16; i++) {
        int nn = nb * 16 + i;
        float s0 = 0.f, s1 = 0.f;
#pragma unroll
        for (int l = 0; l < 32; l++) {
            float u = su[l][nn];
            s0 += swd[2 * c0l][l] * u;
            s1 += swd[2 * c0l + 1][l] * u;
        }
        uint32_t hi, lo;
        pksplit(s0, s1, hi, lo);
        th[(size_t)(n0 + nn) * 512 + c0b + c0l] = hi;
        tl[(size_t)(n0 + nn) * 512 + c0b + c0l] = lo;
    }
}

// ---------------- pre-packed plane GEMM core (ldmatrix fragments) ----------------
#define PP_ST 20
#define PP_A (128*PP_ST)
#define PP_BUF (2*PP_A)
#define SM_PA 0
#define SM_PB (2*PP_BUF)
#define PP_SMEM (4*PP_BUF*4)    // 81920 bytes

#define PP_MAIN(Ah, Al, Bh, Bl, K, COL0)                                                    \
    extern __shared__ uint32_t sm[];                                                         \
    const uint32_t smb = (uint32_t)__cvta_generic_to_shared(sm);                             \
    const int tid = threadIdx.x;                                                             \
    const int w = tid >> 5;                                                                  \
    const int wm = w & 1;                                                                    \
    const int wn = w >> 1;                                                                   \
    const int lane = tid & 31;                                                               \
    const int g = lane >> 2;                                                                 \
    const int t = lane & 3;                                                                  \
    const int lane15 = lane & 15;                                                            \
    const int l7 = lane & 7;                                                                 \
    const int kAsel = (lane >> 4) * 4;                                                       \
    const int kBsel = ((lane >> 3) & 1) * 4;                                                 \
    const int nBsel = (lane >> 4) & 1;                                                       \
    const int row0 = blockIdx.y * 128;                                                       \
    const int col0 = (COL0);                                                                 \
    const int kph = (K) >> 1;                                                                \
    auto fill = [&](int tt, int buf) {                                                       \
        const int kp0 = tt * 16;                                                             \
        _Pragma("unroll")                                                                    \
        for (int i = 0; i < 4; i++) {                                                        \
            int idx = i * 256 + tid;                                                         \
            int plane = idx >> 9;                                                            \
            int r = (idx >> 2) & 127;                                                        \
            int ch = (idx & 3) << 2;                                                         \
            const uint32_t* sa = (plane ? Al : Ah) + (size_t)(row0 + r) * kph + kp0 + ch;    \
            cpa16(smb + (SM_PA + buf * PP_BUF + plane * PP_A + r * PP_ST + ch) * 4, sa);     \
            const uint32_t* sb = (plane ? Bl : Bh) + (size_t)(col0 + r) * kph + kp0 + ch;    \
            cpa16(smb + (SM_PB + buf * PP_BUF + plane * PP_A + r * PP_ST + ch) * 4, sb);     \
        }                                                                                    \
    };                                                                                       \
    float c[4][4][4];                                                                        \
    _Pragma("unroll")                                                                        \
    for (int i = 0; i < 4; i++)                                                              \
        _Pragma("unroll")                                                                    \
        for (int j = 0; j < 4; j++)                                                          \
            _Pragma("unroll")                                                                \
            for (int r = 0; r < 4; r++) c[i][j][r] = 0.f;                                    \
    const int nt = (K) >> 5;                                                                 \
    fill(0, 0);                                                                              \
    asm volatile("cp.async.commit_group;");                                                  \
    asm volatile("cp.async.wait_group 0;");                                                  \
    __syncthreads();                                                                         \
    for (int tt = 0; tt < nt; tt++) {                                                        \
        if (tt + 1 < nt) {                                                                   \
            fill(tt + 1, (tt + 1) & 1);                                                      \
            asm volatile("cp.async.commit_group;");                                          \
        }                                                                                    \
        const uint32_t aBase = SM_PA + (tt & 1) * PP_BUF;                                    \
        const uint32_t bBase = SM_PB + (tt & 1) * PP_BUF;                                    \
        _Pragma("unroll")                                                                    \
        for (int kk = 0; kk < 2; kk++) {                                                     \
            const int kb8 = kk * 8;                                                          \
            uint32_t ah[4][4], al[4][4], bh[2][4], bl[2][4];                                 \
            _Pragma("unroll")                                                                \
            for (int i = 0; i < 4; i++) {                                                    \
                uint32_t offA = (uint32_t)((wm * 64 + i * 16 + lane15) * PP_ST + kb8 + kAsel); \
                ldsm4(ah[i][0], ah[i][1], ah[i][2], ah[i][3], smb + (aBase + offA) * 4);     \
                ldsm4(al[i][0], al[i][1], al[i][2], al[i][3], smb + (aBase + PP_A + offA) * 4); \
            }                                                                                \
            _Pragma("unroll")                                                                \
            for (int jp = 0; jp < 2; jp++) {                                                 \
                uint32_t offB = (uint32_t)((wn * 32 + jp * 16 + nBsel * 8 + l7) * PP_ST + kb8 + kBsel); \
                ldsm4(bh[jp][0], bh[jp][1], bh[jp][2], bh[jp][3], smb + (bBase + offB) * 4); \
                ldsm4(bl[jp][0], bl[jp][1], bl[jp][2], bl[jp][3], smb + (bBase + PP_A + offB) * 4); \
            }                                                                                \
            _Pragma("unroll")                                                                \
            for (int i = 0; i < 4; i++)                                                      \
                _Pragma("unroll")                                                            \
                for (int j = 0; j < 4; j++) {                                                \
                    const int jp = j >> 1;                                                   \
                    const int sb2 = (j & 1) * 2;                                             \
                    mma16(c[i][j], ah[i][0], ah[i][1], ah[i][2], ah[i][3], bh[jp][sb2], bh[jp][sb2 + 1]); \
                    mma16(c[i][j], ah[i][0], ah[i][1], ah[i][2], ah[i][3], bl[jp][sb2], bl[jp][sb2 + 1]); \
                    mma16(c[i][j], al[i][0], al[i][1], al[i][2], al[i][3], bh[jp][sb2], bh[jp][sb2 + 1]); \
                }                                                                            \
        }                                                                                    \
        if (tt + 1 < nt) {                                                                   \
            asm volatile("cp.async.wait_group 0;");                                          \
            __syncthreads();                                                                 \
        }                                                                                    \
    }

// merged Q + KV projection (plane output). grid (12, 32): bx<8 -> Q, else KV.
__global__ __launch_bounds__(256) void mm_proj(const uint32_t* __restrict__ Ah,
                                               const uint32_t* __restrict__ Al,
                                               const uint32_t* __restrict__ wqh,
                                               const uint32_t* __restrict__ wql,
                                               const uint32_t* __restrict__ wkh,
                                               const uint32_t* __restrict__ wkl,
                                               uint32_t* __restrict__ qh,
                                               uint32_t* __restrict__ ql,
                                               uint32_t* __restrict__ kvh,
                                               uint32_t* __restrict__ kvl) {
    const bool isq = blockIdx.x < 8;
    const uint32_t* Bh = isq ? wqh : wkh;
    const uint32_t* Bl = isq ? wql : wkl;
    uint32_t* Ph = isq ? qh : kvh;
    uint32_t* Pl = isq ? ql : kvl;
    const int np = isq ? 512 : 256;
    PP_MAIN(Ah, Al, Bh, Bl, 1024, (isq ? blockIdx.x : blockIdx.x - 8) * 128)
#pragma unroll
    for (int i = 0; i < 4; i++) {
        int r = row0 + wm * 64 + i * 16 + g;
#pragma unroll
        for (int j = 0; j < 4; j++) {
            int cp = (col0 + wn * 32 + j * 8 + t * 2) >> 1;
            uint32_t h0, l0, h1, l1;
            pksplit(c[i][j][0], c[i][j][1], h0, l0);
            pksplit(c[i][j][2], c[i][j][3], h1, l1);
            Ph[(size_t)r * np + cp] = h0;
            Pl[(size_t)r * np + cp] = l0;
            Ph[(size_t)(r + 8) * np + cp] = h1;
            Pl[(size_t)(r + 8) * np + cp] = l1;
        }
    }
}

// fp32-output variant (out projection)
__global__ __launch_bounds__(256) void mm_pp_f32(int N, int K,
                                                 const uint32_t* __restrict__ Ah,
                                                 const uint32_t* __restrict__ Al,
                                                 const uint32_t* __restrict__ Bh,
                                                 const uint32_t* __restrict__ Bl,
                                                 float* __restrict__ C) {
    PP_MAIN(Ah, Al, Bh, Bl, K, blockIdx.x * 128)
#pragma unroll
    for (int i = 0; i < 4; i++) {
        int r = row0 + wm * 64 + i * 16 + g;
#pragma unroll
        for (int j = 0; j < 4; j++) {
            int cc = col0 + wn * 32 + j * 8 + t * 2;
            *(float2*)(C + (size_t)r * N + cc) = make_float2(c[i][j][0], c[i][j][1]);
            *(float2*)(C + (size_t)(r + 8) * N + cc) = make_float2(c[i][j][2], c[i][j][3]);
        }
    }
}

// ---------------- V transpose: KV planes [token][dpair] -> VT planes [d][tokenpair] ----------------
__global__ __launch_bounds__(256) void vtrans_kernel(const uint32_t* __restrict__ kvh,
                                                     const uint32_t* __restrict__ kvl,
                                                     uint32_t* __restrict__ vth,
                                                     uint32_t* __restrict__ vtl) {
    __shared__ uint32_t tile[64][65];
    const int t0 = blockIdx.x * 64;
    const int kvhd = blockIdx.y;
    const int b = blockIdx.z;
    const int tid = threadIdx.x;
#pragma unroll
    for (int p = 0; p < 2; p++) {
        const uint32_t* src = p ? kvl : kvh;
        uint32_t* dst = p ? vtl : vth;
#pragma unroll
        for (int i = 0; i < 16; i++) {
            int idx = i * 256 + tid;
            int r = idx >> 6, cx = idx & 63;
            tile[r][cx] = src[(size_t)(b * SEQ + t0 + r) * 256 + 128 + kvhd * 64 + cx];
        }
        __syncthreads();
#pragma unroll
        for (int i = 0; i < 16; i++) {
            int idx = i * 256 + tid;
            int d = idx >> 5, tpl = idx & 31;
            uint32_t u0 = tile[2 * tpl][d >> 1];
            uint32_t u1 = tile[2 * tpl + 1][d >> 1];
            uint32_t res = (d & 1) ? LOP(u0, u1) : HIP(u0, u1);
            dst[(size_t)((b * N_KV + kvhd) * 128 + d) * 1024 + (t0 >> 1) + tpl] = res;
        }
        __syncthreads();
    }
}

// ---------------- flash attention v6: BR=64, BC=64, 128 threads, 2 CTAs/SM ----------------
#define F6_QS 68
#define F6_KS 68
#define F6_VS 36
#define F6Q 0
#define F6K (2*64*F6_QS)
#define F6V (F6K + 2*64*F6_KS)
#define FA6_SMEM ((F6V + 2*128*F6_VS)*4)     // 106496 bytes -> 2 CTAs/SM

__global__ __launch_bounds__(128, 2) void flash6_kernel(const uint32_t* __restrict__ qh,
                                                        const uint32_t* __restrict__ ql,
                                                        const uint32_t* __restrict__ kvh,
                                                        const uint32_t* __restrict__ kvl,
                                                        const uint32_t* __restrict__ vth,
                                                        const uint32_t* __restrict__ vtl,
                                                        uint32_t* __restrict__ yh,
                                                        uint32_t* __restrict__ yl) {
    extern __shared__ uint32_t sm[];
    const uint32_t smb = (uint32_t)__cvta_generic_to_shared(sm);

    const int qb = (SEQ / 64 - 1) - blockIdx.x;    // heavy tiles first
    const int hq = blockIdx.y;
    const int b  = blockIdx.z;
    const int kvhd = hq >> 2;
    const int tid = threadIdx.x;
    const int w = tid >> 5;                        // 0..3
    const int lane = tid & 31;
    const int g = lane >> 2;
    const int t = lane & 3;
    const int lane15 = lane & 15;
    const int l7 = lane & 7;
    const int kAsel = (lane >> 4) * 4;
    const int kBsel = ((lane >> 3) & 1) * 4;
    const int nBsel = (lane >> 4) & 1;
    const int q0 = qb * 64;

    // ---- fills (128 threads) ----
    auto fillQ = [&]() {
#pragma unroll
        for (int i = 0; i < 16; i++) {
            int idx = i * 128 + tid;              // < 2048
            int plane = idx >> 10;
            int r = (idx >> 4) & 63;
            int ch = (idx & 15) << 2;
            const uint32_t* src = (plane ? ql : qh) + (size_t)(b * SEQ + q0 + r) * 512 + hq * 64 + ch;
            cpa16(smb + (F6Q + plane * (64 * F6_QS) + r * F6_QS + ch) * 4, src);
        }
    };
    auto fillK = [&](int kt) {
#pragma unroll
        for (int i = 0; i < 16; i++) {
            int idx = i * 128 + tid;
            int plane = idx >> 10;
            int r = (idx >> 4) & 63;
            int ch = (idx & 15) << 2;
            const uint32_t* src = (plane ? kvl : kvh) +
                                  (size_t)(b * SEQ + kt * 64 + r) * 256 + kvhd * 64 + ch;
            cpa16(smb + (F6K + plane * (64 * F6_KS) + r * F6_KS + ch) * 4, src);
        }
    };
    auto fillV = [&](int kt) {
#pragma unroll
        for (int i = 0; i < 16; i++) {
            int idx = i * 128 + tid;
            int plane = idx >> 10;
            int d = (idx >> 3) & 127;
            int ch = (idx & 7) << 2;
            const uint32_t* src = (plane ? vtl : vth) +
                                  (size_t)((b * N_KV + kvhd) * 128 + d) * 1024 + kt * 32 + ch;
            cpa16(smb + (F6V + plane * (128 * F6_VS) + d * F6_VS + ch) * 4, src);
        }
    };
    fillQ();
    fillK(0);
    fillV(0);
    asm volatile("cp.async.commit_group;");
    asm volatile("cp.async.wait_group 0;");
    __syncthreads();

    float m0 = -1e30f, m1 = -1e30f, l0 = 0.f, l1 = 0.f;
    float o[16][4];
#pragma unroll
    for (int n = 0; n < 16; n++)
#pragma unroll
        for (int r = 0; r < 4; r++) o[n][r] = 0.f;

    const int rowg = q0 + w * 16 + g;
    const int rb0 = w * 16;

    for (int kc = 0; kc <= qb; kc++) {
        // ---- S = Q @ K^T : warp tile 16 x 64 ----
        float s[8][4];
#pragma unroll
        for (int n = 0; n < 8; n++)
#pragma unroll
            for (int r = 0; r < 4; r++) s[n][r] = 0.f;

#pragma unroll
        for (int kt = 0; kt < 8; kt++) {
            uint32_t ah[4], al[4];
            const uint32_t offQ = (uint32_t)((rb0 + lane15) * F6_QS + kt * 8 + kAsel);
            ldsm4(ah[0], ah[1], ah[2], ah[3], smb + (F6Q + offQ) * 4);
            ldsm4(al[0], al[1], al[2], al[3], smb + (F6Q + 64 * F6_QS + offQ) * 4);
#pragma unroll
            for (int np = 0; np < 4; np++) {
                uint32_t bh[4], bl[4];
                const uint32_t offK = (uint32_t)((np * 16 + nBsel * 8 + l7) * F6_KS + kt * 8 + kBsel);
                ldsm4(bh[0], bh[1], bh[2], bh[3], smb + (F6K + offK) * 4);
                ldsm4(bl[0], bl[1], bl[2], bl[3], smb + (F6K + 64 * F6_KS + offK) * 4);
                mma16(s[2 * np],     ah[0], ah[1], ah[2], ah[3], bh[0], bh[1]);
                mma16(s[2 * np],     ah[0], ah[1], ah[2], ah[3], bl[0], bl[1]);
                mma16(s[2 * np],     al[0], al[1], al[2], al[3], bh[0], bh[1]);
                mma16(s[2 * np + 1], ah[0], ah[1], ah[2], ah[3], bh[2], bh[3]);
                mma16(s[2 * np + 1], ah[0], ah[1], ah[2], ah[3], bl[2], bl[3]);
                mma16(s[2 * np + 1], al[0], al[1], al[2], al[3], bh[2], bh[3]);
            }
        }

        __syncthreads();                       // K consumed
        if (kc < qb) {
            fillK(kc + 1);                     // group A_kc
            asm volatile("cp.async.commit_group;");
        }

        // causal mask on the diagonal tile
        if (kc == qb) {
#pragma unroll
            for (int n = 0; n < 8; n++) {
                int c0 = kc * 64 + n * 8 + 2 * t;
                if (c0 > rowg)          s[n][0] = -1e30f;
                if (c0 + 1 > rowg)      s[n][1] = -1e30f;
                if (c0 > rowg + 8)      s[n][2] = -1e30f;
                if (c0 + 1 > rowg + 8)  s[n][3] = -1e30f;
            }
        }

        // ---- in-warp online softmax ----
        float mx0 = -1e30f, mx1 = -1e30f;
#pragma unroll
        for (int n = 0; n < 8; n++) {
            mx0 = fmaxf(mx0, fmaxf(s[n][0], s[n][1]));
            mx1 = fmaxf(mx1, fmaxf(s[n][2], s[n][3]));
        }
        mx0 = fmaxf(mx0, __shfl_xor_sync(0xffffffffu, mx0, 1));
        mx0 = fmaxf(mx0, __shfl_xor_sync(0xffffffffu, mx0, 2));
        mx1 = fmaxf(mx1, __shfl_xor_sync(0xffffffffu, mx1, 1));
        mx1 = fmaxf(mx1, __shfl_xor_sync(0xffffffffu, mx1, 2));
        float mn0 = fmaxf(m0, mx0), mn1 = fmaxf(m1, mx1);
        float a0 = __expf(m0 - mn0), a1 = __expf(m1 - mn1);
        m0 = mn0; m1 = mn1;
        float rs0 = 0.f, rs1 = 0.f;
#pragma unroll
        for (int n = 0; n < 8; n++) {
            s[n][0] = __expf(s[n][0] - mn0);
            s[n][1] = __expf(s[n][1] - mn0);
            s[n][2] = __expf(s[n][2] - mn1);
            s[n][3] = __expf(s[n][3] - mn1);
            rs0 += s[n][0] + s[n][1];
            rs1 += s[n][2] + s[n][3];
        }
        rs0 += __shfl_xor_sync(0xffffffffu, rs0, 1);
        rs0 += __shfl_xor_sync(0xffffffffu, rs0, 2);
        rs1 += __shfl_xor_sync(0xffffffffu, rs1, 1);
        rs1 += __shfl_xor_sync(0xffffffffu, rs1, 2);
        l0 = l0 * a0 + rs0;
        l1 = l1 * a1 + rs1;
#pragma unroll
        for (int n = 0; n < 16; n++) {
            o[n][0] *= a0; o[n][1] *= a0;
            o[n][2] *= a1; o[n][3] *= a1;
        }

        // pack P fragments (4 kt-chunks of 16 tokens)
        uint32_t phi[4][4], plo[4][4];
#pragma unroll
        for (int kt = 0; kt < 4; kt++) {
            pksplit(s[2 * kt][0], s[2 * kt][1], phi[kt][0], plo[kt][0]);
            pksplit(s[2 * kt][2], s[2 * kt][3], phi[kt][1], plo[kt][1]);
            pksplit(s[2 * kt + 1][0], s[2 * kt + 1][1], phi[kt][2], plo[kt][2]);
            pksplit(s[2 * kt + 1][2], s[2 * kt + 1][3], phi[kt][3], plo[kt][3]);
        }

        // V(kc) readiness: prologue (kc=0) already waited; else retire B_{kc-1}
        if (kc == qb) { asm volatile("cp.async.wait_group 0;"); }
        else          { asm volatile("cp.async.wait_group 1;"); }
        __syncthreads();

        // ---- O += P @ V : warp tile 16 x 128, k=64 ----
#pragma unroll
        for (int kt = 0; kt < 4; kt++) {
            const int koff = kt * 8 + kBsel;
#pragma unroll
            for (int np = 0; np < 8; np++) {
                uint32_t vh[4], vl[4];
                const uint32_t offV = (uint32_t)((np * 16 + nBsel * 8 + l7) * F6_VS + koff);
                ldsm4(vh[0], vh[1], vh[2], vh[3], smb + (F6V + offV) * 4);
                ldsm4(vl[0], vl[1], vl[2], vl[3], smb + (F6V + 128 * F6_VS + offV) * 4);
                mma16(o[2 * np],     phi[kt][0], phi[kt][1], phi[kt][2], phi[kt][3], vh[0], vh[1]);
                mma16(o[2 * np],     phi[kt][0], phi[kt][1], phi[kt][2], phi[kt][3], vl[0], vl[1]);
                mma16(o[2 * np],     plo[kt][0], plo[kt][1], plo[kt][2], plo[kt][3], vh[0], vh[1]);
                mma16(o[2 * np + 1], phi[kt][0], phi[kt][1], phi[kt][2], phi[kt][3], vh[2], vh[3]);
                mma16(o[2 * np + 1], phi[kt][0], phi[kt][1], phi[kt][2], phi[kt][3], vl[2], vl[3]);
                mma16(o[2 * np + 1], plo[kt][0], plo[kt][1], plo[kt][2], plo[kt][3], vh[2], vh[3]);
            }
        }

        __syncthreads();                       // V consumed
        if (kc < qb) {
            fillV(kc + 1);                     // group B_kc
            asm volatile("cp.async.commit_group;");
            asm volatile("cp.async.wait_group 1;");  // retire A_kc -> K(kc+1) ready
            __syncthreads();
        }
    }

    // epilogue: emit y planes (pairs along d == out-proj K)
    const int row = w * 16 + g;
    float inv0 = 1.f / l0, inv1 = 1.f / l1;
    uint32_t* yh0 = yh + (size_t)(b * SEQ + q0 + row) * 512;
    uint32_t* yl0 = yl + (size_t)(b * SEQ + q0 + row) * 512;
    uint32_t* yh1 = yh + (size_t)(b * SEQ + q0 + row + 8) * 512;
    uint32_t* yl1 = yl + (size_t)(b * SEQ + q0 + row + 8) * 512;
#pragma unroll
    for (int n = 0; n < 16; n++) {
        int cp = hq * 64 + n * 4 + t;
        uint32_t h, l;
        pksplit(o[n][0] * inv0, o[n][1] * inv0, h, l);
        yh0[cp] = h; yl0[cp] = l;
        pksplit(o[n][2] * inv1, o[n][3] * inv1, h, l);
        yh1[cp] = h; yl1[cp] = l;
    }
}

// ---------------- launch ----------------
extern "C" void kernel_launch(void* const* d_in, const int* in_sizes, int n_in,
                              void* d_out, int out_size) {
    const float* x   = (const float*)d_in[0];
    const float* wq  = (const float*)d_in[1];
    const float* wkd = (const float*)d_in[2];
    const float* wvd = (const float*)d_in[3];
    const float* wku = (const float*)d_in[4];
    const float* wvu = (const float*)d_in[5];
    const float* wo  = (const float*)d_in[6];
    float* out = (float*)d_out;

    float* scratch = nullptr;
    cudaGetSymbolAddress((void**)&scratch, g_scratch);
    uint32_t* xh   = (uint32_t*)(scratch + OFF_XH);
    uint32_t* xl   = (uint32_t*)(scratch + OFF_XL);
    uint32_t* wqth = (uint32_t*)(scratch + OFF_WQT_H);
    uint32_t* wqtl = (uint32_t*)(scratch + OFF_WQT_L);
    uint32_t* woth = (uint32_t*)(scratch + OFF_WOT_H);
    uint32_t* wotl = (uint32_t*)(scratch + OFF_WOT_L);
    uint32_t* wkth = (uint32_t*)(scratch + OFF_WKT_H);
    uint32_t* wktl = (uint32_t*)(scratch + OFF_WKT_L);
    uint32_t* qhg  = (uint32_t*)(scratch + OFF_QH);
    uint32_t* qlg  = (uint32_t*)(scratch + OFF_QL);
    uint32_t* kvhg = (uint32_t*)(scratch + OFF_KVH);
    uint32_t* kvlg = (uint32_t*)(scratch + OFF_KVL);
    uint32_t* vthg = (uint32_t*)(scratch + OFF_VTH);
    uint32_t* vtlg = (uint32_t*)(scratch + OFF_VTL);
    uint32_t* yhg  = (uint32_t*)(scratch + OFF_YH);
    uint32_t* ylg  = (uint32_t*)(scratch + OFF_YL);

    const float scale = 0.08838834764831845f;   // 1/sqrt(128)

    // prep: pack operands into split-bf16 planes (scale folded into wq)
    pack_x_kernel<<<8192, 256>>>(x, xh, xl);
    packT_kernel<<<dim3(8, 16), 256>>>(wq, 1024, wqth, wqtl, scale);
    packT_kernel<<<dim3(8, 16), 256>>>(wo, 1024, woth, wotl, 1.0f);
    eff_weightsT_kernel<<<dim3(8, 8), 256>>>(wkd, wvd, wku, wvu, wkth, wktl);

    cudaFuncSetAttribute(mm_proj, cudaFuncAttributeMaxDynamicSharedMemorySize, PP_SMEM);
    cudaFuncSetAttribute(mm_pp_f32, cudaFuncAttributeMaxDynamicSharedMemorySize, PP_SMEM);

    // merged Q + KV projections
    mm_proj<<<dim3(12, 32), 256, PP_SMEM>>>(xh, xl, wqth, wqtl, wkth, wktl,
                                            qhg, qlg, kvhg, kvlg);

    vtrans_kernel<<<dim3(SEQ / 64, N_KV, BATCH), 256>>>(kvhg, kvlg, vthg, vtlg);

    cudaFuncSetAttribute(flash6_kernel, cudaFuncAttributeMaxDynamicSharedMemorySize, FA6_SMEM);
    flash6_kernel<<<dim3(SEQ / 64, N_HEADS, BATCH), 128, FA6_SMEM>>>(qhg, qlg, kvhg, kvlg,
                                                                     vthg, vtlg, yhg, ylg);

    // output projection
    mm_pp_f32<<<dim3(8, 32), 256, PP_SMEM>>>(1024, 1024, yhg, ylg, woth, wotl, out);
}